// round 1
// baseline (speedup 1.0000x reference)
#include <cuda_runtime.h>
#include <cuda_bf16.h>
#include <math.h>

// ---------------- problem constants ----------------
#define L       2048
#define D       768
#define ED      1536
#define NL      4
#define NST     16
#define DTR     48
#define DXP     80        // DT_RANK + 2*D_STATE
#define VOCAB   32000
#define DCONV   4
#define CHUNK   64
#define NCHUNK  (L / CHUNK)   // 32

// ---------------- scratch (device globals; no allocation allowed) ----------------
__device__ float g_x    [L * D];        // residual stream
__device__ float g_xn   [L * D];        // normed
__device__ float g_xz   [L * 2 * ED];   // in_proj output
__device__ float g_xb   [L * ED];       // conv+silu output
__device__ float g_dbc  [L * DXP];      // x_proj output
__device__ float g_delta[L * ED];       // softplus(dt)
__device__ float g_yz   [L * ED];       // gated scan output
__device__ float g_cp   [NCHUNK * ED * NST];   // chunk products
__device__ float g_cs   [NCHUNK * ED * NST];   // chunk local scan ends
__device__ float g_cc   [NCHUNK * ED * NST];   // chunk carry-in

// ---------------- embedding gather ----------------
__global__ void embed_k(const int* __restrict__ tok, const float* __restrict__ emb,
                        float* __restrict__ x) {
    int i = blockIdx.x * blockDim.x + threadIdx.x;
    if (i >= L * D) return;
    int t = i / D, d = i % D;
    x[i] = emb[(size_t)tok[t] * D + d];
}

// ---------------- RMSNorm (one block per row) ----------------
__global__ void rmsnorm_k(const float* __restrict__ x, const float* __restrict__ w,
                          float* __restrict__ out) {
    int t = blockIdx.x;
    const float* xr = x + (size_t)t * D;
    float s = 0.f;
    for (int d = threadIdx.x; d < D; d += 256) { float v = xr[d]; s += v * v; }
    __shared__ float red[256];
    red[threadIdx.x] = s;
    __syncthreads();
    for (int o = 128; o > 0; o >>= 1) {
        if (threadIdx.x < o) red[threadIdx.x] += red[threadIdx.x + o];
        __syncthreads();
    }
    float inv = rsqrtf(red[0] / (float)D + 1e-5f);
    for (int d = threadIdx.x; d < D; d += 256)
        out[(size_t)t * D + d] = xr[d] * inv * w[d];
}

// ---------------- depthwise causal conv1d + silu ----------------
__global__ void conv_silu_k(const float* __restrict__ xz, const float* __restrict__ w,
                            const float* __restrict__ b, float* __restrict__ xb) {
    int i = blockIdx.x * blockDim.x + threadIdx.x;
    if (i >= L * ED) return;
    int t = i / ED, e = i % ED;
    const float* wr = w + e * DCONV;
    float acc = b[e];
#pragma unroll
    for (int j = 0; j < DCONV; j++) {
        int tt = t - (DCONV - 1) + j;
        if (tt >= 0) acc = fmaf(xz[(size_t)tt * (2 * ED) + e], wr[j], acc);
    }
    xb[i] = acc / (1.f + __expf(-acc));   // silu
}

// ---------------- generic fp32 GEMM: C[M,N] = A[M,K] @ B[N,K]^T ----------------
// epi: 0 = plain store, 1 = softplus(acc + aux[n]), 2 = C[m,n] += acc (residual)
#define BM 128
#define BN 128
#define BK 8

__global__ __launch_bounds__(256) void gemm_k(
    const float* __restrict__ A, const float* __restrict__ B, float* __restrict__ C,
    int M, int N, int K, int lda, int ldb, int ldc,
    int epi, const float* __restrict__ aux)
{
    __shared__ float As[BK][BM];
    __shared__ float Bs[BK][BN + 4];
    int tid = threadIdx.x;
    int m0 = blockIdx.y * BM;
    int n0 = blockIdx.x * BN;
    int lm = tid >> 1;              // 0..127 : row within tile
    int lk = (tid & 1) << 2;        // 0 or 4 : k offset
    int tx = tid & 15;
    int ty = tid >> 4;

    float acc[8][8];
#pragma unroll
    for (int i = 0; i < 8; i++)
#pragma unroll
        for (int j = 0; j < 8; j++) acc[i][j] = 0.f;

    const float* Ap = A + (size_t)(m0 + lm) * lda + lk;
    const float* Bp = B + (size_t)(n0 + lm) * ldb + lk;
    bool bok = (n0 + lm) < N;

    for (int k0 = 0; k0 < K; k0 += BK) {
        float4 av = *(const float4*)(Ap + k0);
        float4 bv = make_float4(0.f, 0.f, 0.f, 0.f);
        if (bok) bv = *(const float4*)(Bp + k0);
        __syncthreads();
        As[lk + 0][lm] = av.x; As[lk + 1][lm] = av.y;
        As[lk + 2][lm] = av.z; As[lk + 3][lm] = av.w;
        Bs[lk + 0][lm] = bv.x; Bs[lk + 1][lm] = bv.y;
        Bs[lk + 2][lm] = bv.z; Bs[lk + 3][lm] = bv.w;
        __syncthreads();
#pragma unroll
        for (int k = 0; k < BK; k++) {
            float ar[8], br[8];
            *(float4*)&ar[0] = *(const float4*)&As[k][ty * 8];
            *(float4*)&ar[4] = *(const float4*)&As[k][ty * 8 + 4];
            *(float4*)&br[0] = *(const float4*)&Bs[k][tx * 8];
            *(float4*)&br[4] = *(const float4*)&Bs[k][tx * 8 + 4];
#pragma unroll
            for (int i = 0; i < 8; i++)
#pragma unroll
                for (int j = 0; j < 8; j++)
                    acc[i][j] = fmaf(ar[i], br[j], acc[i][j]);
        }
    }

#pragma unroll
    for (int i = 0; i < 8; i++) {
        int m = m0 + ty * 8 + i;
        float* Crow = C + (size_t)m * ldc;
#pragma unroll
        for (int j = 0; j < 8; j++) {
            int n = n0 + tx * 8 + j;
            if (n < N) {
                float v = acc[i][j];
                if (epi == 1) {
                    v += aux[n];
                    v = (v > 20.f) ? v : log1pf(__expf(v));   // softplus
                } else if (epi == 2) {
                    v += Crow[n];
                }
                Crow[n] = v;
            }
        }
    }
}

// ---------------- selective scan: chunked parallel scan ----------------
// pass 1: per (chunk, channel) compute local scan (h0 = 0) and cumulative a-product
__global__ void scan1_k(const float* __restrict__ delta, const float* __restrict__ xb,
                        const float* __restrict__ dbc, const float* __restrict__ A_log,
                        float* __restrict__ cp, float* __restrict__ cs) {
    int i = blockIdx.x * blockDim.x + threadIdx.x;
    if (i >= NCHUNK * ED) return;
    int c = i / ED, e = i % ED;
    float A[NST], h[NST], p[NST];
#pragma unroll
    for (int n = 0; n < NST; n++) {
        A[n] = -__expf(A_log[e * NST + n]);
        h[n] = 0.f; p[n] = 1.f;
    }
    int t0 = c * CHUNK;
    for (int t = t0; t < t0 + CHUNK; t++) {
        float d  = delta[(size_t)t * ED + e];
        float xv = xb[(size_t)t * ED + e];
        float dx = d * xv;
        const float* Bt = dbc + (size_t)t * DXP + DTR;
#pragma unroll
        for (int n = 0; n < NST; n++) {
            float a = __expf(d * A[n]);
            p[n] *= a;
            h[n] = fmaf(a, h[n], dx * Bt[n]);
        }
    }
    size_t o = (size_t)i * NST;
#pragma unroll
    for (int n = 0; n < NST; n++) { cp[o + n] = p[n]; cs[o + n] = h[n]; }
}

// pass 1b: sequential combine over chunks → carry-in state per chunk
__global__ void carry_k(const float* __restrict__ cp, const float* __restrict__ cs,
                        float* __restrict__ cc) {
    int i = blockIdx.x * blockDim.x + threadIdx.x;   // i = e*NST + n
    if (i >= ED * NST) return;
    float H = 0.f;
    for (int c = 0; c < NCHUNK; c++) {
        size_t idx = (size_t)c * ED * NST + i;
        cc[idx] = H;
        H = fmaf(cp[idx], H, cs[idx]);
    }
}

// pass 2: re-run local scan with correct carry-in; fuse y = h·C + x*D, gate with silu(z)
__global__ void scan2_k(const float* __restrict__ delta, const float* __restrict__ xb,
                        const float* __restrict__ dbc, const float* __restrict__ A_log,
                        const float* __restrict__ cc, const float* __restrict__ Dp,
                        const float* __restrict__ xz, float* __restrict__ yz) {
    int i = blockIdx.x * blockDim.x + threadIdx.x;
    if (i >= NCHUNK * ED) return;
    int c = i / ED, e = i % ED;
    float A[NST], h[NST];
#pragma unroll
    for (int n = 0; n < NST; n++) {
        A[n] = -__expf(A_log[e * NST + n]);
        h[n] = cc[(size_t)i * NST + n];
    }
    float Dv = Dp[e];
    int t0 = c * CHUNK;
    for (int t = t0; t < t0 + CHUNK; t++) {
        float d  = delta[(size_t)t * ED + e];
        float xv = xb[(size_t)t * ED + e];
        float dx = d * xv;
        const float* Bt = dbc + (size_t)t * DXP + DTR;
        const float* Ct = dbc + (size_t)t * DXP + DTR + NST;
        float y = 0.f;
#pragma unroll
        for (int n = 0; n < NST; n++) {
            float a = __expf(d * A[n]);
            h[n] = fmaf(a, h[n], dx * Bt[n]);
            y = fmaf(h[n], Ct[n], y);
        }
        float zv = xz[(size_t)t * (2 * ED) + ED + e];
        float sz = zv / (1.f + __expf(-zv));      // silu(z)
        yz[(size_t)t * ED + e] = (y + xv * Dv) * sz;
    }
}

// ---------------- host orchestration ----------------
extern "C" void kernel_launch(void* const* d_in, const int* in_sizes, int n_in,
                              void* d_out, int out_size) {
    const int*   tokens  = (const int*)d_in[0];
    const float* emb     = (const float*)d_in[1];
    const float* norm_w  = (const float*)d_in[2];
    const float* in_proj = (const float*)d_in[3];
    const float* conv_w  = (const float*)d_in[4];
    const float* conv_b  = (const float*)d_in[5];
    const float* x_proj  = (const float*)d_in[6];
    const float* dt_w    = (const float*)d_in[7];
    const float* dt_b    = (const float*)d_in[8];
    const float* A_log   = (const float*)d_in[9];
    const float* Dp      = (const float*)d_in[10];
    const float* out_prj = (const float*)d_in[11];
    const float* norm_f  = (const float*)d_in[12];
    const float* lm_head = (const float*)d_in[13];
    float* logits = (float*)d_out;

    float *x, *xn, *xz, *xb, *dbc, *delta, *yz, *cp, *cs, *cc;
    cudaGetSymbolAddress((void**)&x,     g_x);
    cudaGetSymbolAddress((void**)&xn,    g_xn);
    cudaGetSymbolAddress((void**)&xz,    g_xz);
    cudaGetSymbolAddress((void**)&xb,    g_xb);
    cudaGetSymbolAddress((void**)&dbc,   g_dbc);
    cudaGetSymbolAddress((void**)&delta, g_delta);
    cudaGetSymbolAddress((void**)&yz,    g_yz);
    cudaGetSymbolAddress((void**)&cp,    g_cp);
    cudaGetSymbolAddress((void**)&cs,    g_cs);
    cudaGetSymbolAddress((void**)&cc,    g_cc);

    embed_k<<<(L * D + 255) / 256, 256>>>(tokens, emb, x);

    for (int l = 0; l < NL; l++) {
        rmsnorm_k<<<L, 256>>>(x, norm_w + l * D, xn);

        // xz = xn @ in_proj^T   (2048 x 3072, K=768)
        gemm_k<<<dim3((2 * ED) / BN, L / BM), 256>>>(
            xn, in_proj + (size_t)l * 2 * ED * D, xz,
            L, 2 * ED, D, D, D, 2 * ED, 0, nullptr);

        conv_silu_k<<<(L * ED + 255) / 256, 256>>>(
            xz, conv_w + (size_t)l * ED * DCONV, conv_b + l * ED, xb);

        // dbc = xb @ x_proj^T   (2048 x 80, K=1536)
        gemm_k<<<dim3((DXP + BN - 1) / BN, L / BM), 256>>>(
            xb, x_proj + (size_t)l * DXP * ED, dbc,
            L, DXP, ED, ED, ED, DXP, 0, nullptr);

        // delta = softplus(dbc[:, :48] @ dt_w^T + dt_b)   (2048 x 1536, K=48)
        gemm_k<<<dim3(ED / BN, L / BM), 256>>>(
            dbc, dt_w + (size_t)l * ED * DTR, delta,
            L, ED, DTR, DXP, DTR, ED, 1, dt_b + l * ED);

        // selective scan (chunked parallel scan)
        scan1_k<<<(NCHUNK * ED) / 256, 256>>>(delta, xb, dbc,
                                              A_log + (size_t)l * ED * NST, cp, cs);
        carry_k<<<(ED * NST) / 256, 256>>>(cp, cs, cc);
        scan2_k<<<(NCHUNK * ED) / 256, 256>>>(delta, xb, dbc,
                                              A_log + (size_t)l * ED * NST, cc,
                                              Dp + l * ED, xz, yz);

        // x += yz @ out_proj^T   (2048 x 768, K=1536)
        gemm_k<<<dim3(D / BN, L / BM), 256>>>(
            yz, out_prj + (size_t)l * D * ED, x,
            L, D, ED, ED, ED, D, 2, nullptr);
    }

    rmsnorm_k<<<L, 256>>>(x, norm_f, xn);

    // logits = xn @ lm_head^T   (2048 x 32000, K=768)
    gemm_k<<<dim3(VOCAB / BN, L / BM), 256>>>(
        xn, lm_head, logits,
        L, VOCAB, D, D, D, VOCAB, 0, nullptr);
}

// round 3
// speedup vs baseline: 1.6275x; 1.6275x over previous
#include <cuda_runtime.h>
#include <cuda_bf16.h>
#include <math.h>
#include <cstdint>

// ---------------- problem constants ----------------
#define L       2048
#define D       768
#define ED      1536
#define NL      4
#define NST     16
#define DTR     48
#define DXP     80
#define VOCAB   32000
#define DCONV   4
#define CHUNK   64
#define NCHUNK  (L / CHUNK)
#define KSPLIT  8

// ---------------- scratch ----------------
__device__ __align__(256) float g_x    [L * D];
__device__ __align__(256) float g_xz   [L * 2 * ED];
__device__ __align__(256) float g_xb   [L * ED];
__device__ __align__(256) float g_dbc  [L * DXP];
__device__ __align__(256) float g_delta[L * ED];
__device__ __align__(256) float g_part [KSPLIT * L * DXP];
__device__ __align__(256) float g_cp   [NCHUNK * ED * NST];
__device__ __align__(256) float g_cs   [NCHUNK * ED * NST];
__device__ __align__(256) float g_cc   [NCHUNK * ED * NST];
__device__ __align__(256) __nv_bfloat16 g_ah[L * ED];
__device__ __align__(256) __nv_bfloat16 g_al[L * ED];
__device__ __align__(256) __nv_bfloat16 g_wh[VOCAB * D];
__device__ __align__(256) __nv_bfloat16 g_wl[VOCAB * D];

// ---------------- helpers ----------------
__device__ __forceinline__ uint32_t smem_u32(const void* p) {
    uint32_t a;
    asm("{ .reg .u64 t; cvta.to.shared.u64 t, %1; cvt.u32.u64 %0, t; }" : "=r"(a) : "l"(p));
    return a;
}
__device__ __forceinline__ void ldsm4(uint32_t* r, uint32_t addr) {
    asm volatile("ldmatrix.sync.aligned.m8n8.x4.shared.b16 {%0,%1,%2,%3}, [%4];"
                 : "=r"(r[0]), "=r"(r[1]), "=r"(r[2]), "=r"(r[3]) : "r"(addr));
}
__device__ __forceinline__ void ldsm2(uint32_t* r, uint32_t addr) {
    asm volatile("ldmatrix.sync.aligned.m8n8.x2.shared.b16 {%0,%1}, [%2];"
                 : "=r"(r[0]), "=r"(r[1]) : "r"(addr));
}
__device__ __forceinline__ void mma_bf16(float* d, const uint32_t* a, const uint32_t* b) {
    asm volatile(
        "mma.sync.aligned.m16n8k16.row.col.f32.bf16.bf16.f32 "
        "{%0,%1,%2,%3}, {%4,%5,%6,%7}, {%8,%9}, {%0,%1,%2,%3};"
        : "+f"(d[0]), "+f"(d[1]), "+f"(d[2]), "+f"(d[3])
        : "r"(a[0]), "r"(a[1]), "r"(a[2]), "r"(a[3]), "r"(b[0]), "r"(b[1]));
}

// ---------------- embedding ----------------
__global__ void embed_k(const int* __restrict__ tok, const float* __restrict__ emb,
                        float* __restrict__ x) {
    int i = blockIdx.x * blockDim.x + threadIdx.x;
    if (i >= L * D) return;
    int t = i / D, d = i % D;
    x[i] = emb[(size_t)tok[t] * D + d];
}

// ---------------- fp32 -> bf16 hi/lo split ----------------
__global__ void split4_k(const float4* __restrict__ src, __nv_bfloat162* __restrict__ hi,
                         __nv_bfloat162* __restrict__ lo, int n4) {
    int i = blockIdx.x * blockDim.x + threadIdx.x;
    if (i >= n4) return;
    float4 v = src[i];
    __nv_bfloat16 hx = __float2bfloat16(v.x), hy = __float2bfloat16(v.y);
    __nv_bfloat16 hz = __float2bfloat16(v.z), hw = __float2bfloat16(v.w);
    hi[2 * i]     = __nv_bfloat162(hx, hy);
    hi[2 * i + 1] = __nv_bfloat162(hz, hw);
    lo[2 * i]     = __nv_bfloat162(__float2bfloat16(v.x - __bfloat162float(hx)),
                                   __float2bfloat16(v.y - __bfloat162float(hy)));
    lo[2 * i + 1] = __nv_bfloat162(__float2bfloat16(v.z - __bfloat162float(hz)),
                                   __float2bfloat16(v.w - __bfloat162float(hw)));
}

// ---------------- RMSNorm -> bf16 hi/lo ----------------
__global__ void rmsnorm_split_k(const float* __restrict__ x, const float* __restrict__ w,
                                __nv_bfloat16* __restrict__ oh, __nv_bfloat16* __restrict__ ol) {
    int t = blockIdx.x;
    const float* xr = x + (size_t)t * D;
    float s = 0.f;
    for (int d = threadIdx.x; d < D; d += 256) { float v = xr[d]; s += v * v; }
    __shared__ float red[256];
    red[threadIdx.x] = s;
    __syncthreads();
    for (int o = 128; o > 0; o >>= 1) {
        if (threadIdx.x < o) red[threadIdx.x] += red[threadIdx.x + o];
        __syncthreads();
    }
    float inv = rsqrtf(red[0] / (float)D + 1e-5f);
    for (int d = threadIdx.x; d < D; d += 256) {
        float v = xr[d] * inv * w[d];
        __nv_bfloat16 h = __float2bfloat16(v);
        oh[(size_t)t * D + d] = h;
        ol[(size_t)t * D + d] = __float2bfloat16(v - __bfloat162float(h));
    }
}

// ---------------- depthwise causal conv1d + silu ----------------
__global__ void conv_silu_k(const float* __restrict__ xz, const float* __restrict__ w,
                            const float* __restrict__ b, float* __restrict__ xb) {
    int i = blockIdx.x * blockDim.x + threadIdx.x;
    if (i >= L * ED) return;
    int t = i / ED, e = i % ED;
    const float* wr = w + e * DCONV;
    float acc = b[e];
#pragma unroll
    for (int j = 0; j < DCONV; j++) {
        int tt = t - (DCONV - 1) + j;
        if (tt >= 0) acc = fmaf(xz[(size_t)tt * (2 * ED) + e], wr[j], acc);
    }
    xb[i] = acc / (1.f + __expf(-acc));
}

// ---------------- bf16 3-term split GEMM via mma.sync ----------------
// C[128 x 128] per CTA. C = Ah*Bh^T + Al*Bh^T + Ah*Bl^T (fp32 accum).
// A: [M,K] bf16, B: [N,K] bf16, K % 32 == 0, M,N % 128 == 0.
// EPI: 0 = store, 2 = C += acc
#define ROWE 40
#define ROWB 80

template<int EPI>
__global__ __launch_bounds__(256) void hgemm_k(
    const __nv_bfloat16* __restrict__ Ah, const __nv_bfloat16* __restrict__ Al,
    const __nv_bfloat16* __restrict__ Bh, const __nv_bfloat16* __restrict__ Bl,
    float* __restrict__ C, int K, int ldc)
{
    __shared__ __nv_bfloat16 sm[4 * 128 * ROWE];
    __nv_bfloat16* sAh = sm;
    __nv_bfloat16* sAl = sm + 128 * ROWE;
    __nv_bfloat16* sBh = sm + 2 * 128 * ROWE;
    __nv_bfloat16* sBl = sm + 3 * 128 * ROWE;

    int tid = threadIdx.x, lane = tid & 31, wid = tid >> 5;
    int m0 = blockIdx.x * 128, n0 = blockIdx.y * 128;
    int wm = (wid & 1) * 64, wn = (wid >> 1) * 32;

    int lr = tid >> 2;            // 0..63
    int lk = (tid & 3) * 8;       // elem offset within 32-chunk

    const __nv_bfloat16* gAh0 = Ah + (size_t)(m0 + lr) * K + lk;
    const __nv_bfloat16* gAh1 = Ah + (size_t)(m0 + lr + 64) * K + lk;
    const __nv_bfloat16* gAl0 = Al + (size_t)(m0 + lr) * K + lk;
    const __nv_bfloat16* gAl1 = Al + (size_t)(m0 + lr + 64) * K + lk;
    const __nv_bfloat16* gBh0 = Bh + (size_t)(n0 + lr) * K + lk;
    const __nv_bfloat16* gBh1 = Bh + (size_t)(n0 + lr + 64) * K + lk;
    const __nv_bfloat16* gBl0 = Bl + (size_t)(n0 + lr) * K + lk;
    const __nv_bfloat16* gBl1 = Bl + (size_t)(n0 + lr + 64) * K + lk;

    uint32_t sAh_u = smem_u32(sAh), sAl_u = smem_u32(sAl);
    uint32_t sBh_u = smem_u32(sBh), sBl_u = smem_u32(sBl);
    uint32_t st0 = (uint32_t)(lr * ROWB + lk * 2);
    uint32_t st1 = st0 + 64 * ROWB;

    // ldmatrix address components
    uint32_t aOff = (uint32_t)((wm + (lane & 15)) * ROWB + (lane >> 4) * 16);
    uint32_t bOff = (uint32_t)((wn + (lane & 7)) * ROWB + ((lane >> 3) & 1) * 16);

    float acc[4][4][4];
#pragma unroll
    for (int i = 0; i < 4; i++)
#pragma unroll
        for (int j = 0; j < 4; j++)
#pragma unroll
            for (int r = 0; r < 4; r++) acc[i][j][r] = 0.f;

    // preload chunk 0
    uint4 rAh0 = *(const uint4*)gAh0, rAh1 = *(const uint4*)gAh1;
    uint4 rAl0 = *(const uint4*)gAl0, rAl1 = *(const uint4*)gAl1;
    uint4 rBh0 = *(const uint4*)gBh0, rBh1 = *(const uint4*)gBh1;
    uint4 rBl0 = *(const uint4*)gBl0, rBl1 = *(const uint4*)gBl1;

    for (int k0 = 0; k0 < K; k0 += 32) {
        __syncthreads();
        *(uint4*)((char*)sAh + st0) = rAh0; *(uint4*)((char*)sAh + st1) = rAh1;
        *(uint4*)((char*)sAl + st0) = rAl0; *(uint4*)((char*)sAl + st1) = rAl1;
        *(uint4*)((char*)sBh + st0) = rBh0; *(uint4*)((char*)sBh + st1) = rBh1;
        *(uint4*)((char*)sBl + st0) = rBl0; *(uint4*)((char*)sBl + st1) = rBl1;
        __syncthreads();

        int kn = (k0 + 32 < K) ? (k0 + 32) : 0;   // clamp: dummy reload of k=0 on last iter
        rAh0 = *(const uint4*)(gAh0 + kn); rAh1 = *(const uint4*)(gAh1 + kn);
        rAl0 = *(const uint4*)(gAl0 + kn); rAl1 = *(const uint4*)(gAl1 + kn);
        rBh0 = *(const uint4*)(gBh0 + kn); rBh1 = *(const uint4*)(gBh1 + kn);
        rBl0 = *(const uint4*)(gBl0 + kn); rBl1 = *(const uint4*)(gBl1 + kn);

#pragma unroll
        for (int kk = 0; kk < 2; kk++) {
            uint32_t kb = kk * 32;   // byte offset of k-step (16 elems)
            uint32_t bh[4][2], bl[4][2];
#pragma unroll
            for (int nt = 0; nt < 4; nt++) {
                uint32_t off = bOff + nt * 8 * ROWB + kb;
                ldsm2(bh[nt], sBh_u + off);
                ldsm2(bl[nt], sBl_u + off);
            }
#pragma unroll
            for (int mt = 0; mt < 4; mt++) {
                uint32_t off = aOff + mt * 16 * ROWB + kb;
                uint32_t ah[4], al[4];
                ldsm4(ah, sAh_u + off);
                ldsm4(al, sAl_u + off);
#pragma unroll
                for (int nt = 0; nt < 4; nt++) {
                    mma_bf16(acc[mt][nt], ah, bh[nt]);
                    mma_bf16(acc[mt][nt], al, bh[nt]);
                    mma_bf16(acc[mt][nt], ah, bl[nt]);
                }
            }
        }
    }

    // epilogue
    int er = m0 + wm + (lane >> 2);
    int ec = n0 + wn + (lane & 3) * 2;
#pragma unroll
    for (int mt = 0; mt < 4; mt++) {
#pragma unroll
        for (int nt = 0; nt < 4; nt++) {
            float* p0 = C + (size_t)(er + mt * 16) * ldc + ec + nt * 8;
            float* p1 = p0 + 8 * ldc;
            float d0 = acc[mt][nt][0], d1 = acc[mt][nt][1];
            float d2 = acc[mt][nt][2], d3 = acc[mt][nt][3];
            if (EPI == 2) {
                float2 o0 = *(float2*)p0, o1 = *(float2*)p1;
                d0 += o0.x; d1 += o0.y; d2 += o1.x; d3 += o1.y;
            }
            *(float2*)p0 = make_float2(d0, d1);
            *(float2*)p1 = make_float2(d2, d3);
        }
    }
}

// ---------------- fp32 GEMM (small shapes) ----------------
#define BM 128
#define BN 128
#define BK 8
__global__ __launch_bounds__(256) void gemm_k(
    const float* __restrict__ A, const float* __restrict__ B, float* __restrict__ C,
    int M, int N, int K, int lda, int ldb, int ldc,
    int epi, const float* __restrict__ aux, int kstride)
{
    int z = blockIdx.z;
    A += (size_t)z * kstride;
    B += (size_t)z * kstride;
    C += (size_t)z * (size_t)M * ldc;

    __shared__ float As[BK][BM];
    __shared__ float Bs[BK][BN + 4];
    int tid = threadIdx.x;
    int m0 = blockIdx.y * BM;
    int n0 = blockIdx.x * BN;
    int lm = tid >> 1;
    int lk = (tid & 1) << 2;
    int tx = tid & 15;
    int ty = tid >> 4;

    float acc[8][8];
#pragma unroll
    for (int i = 0; i < 8; i++)
#pragma unroll
        for (int j = 0; j < 8; j++) acc[i][j] = 0.f;

    const float* Ap = A + (size_t)(m0 + lm) * lda + lk;
    const float* Bp = B + (size_t)(n0 + lm) * ldb + lk;
    bool bok = (n0 + lm) < N;

    for (int k0 = 0; k0 < K; k0 += BK) {
        float4 av = *(const float4*)(Ap + k0);
        float4 bv = make_float4(0.f, 0.f, 0.f, 0.f);
        if (bok) bv = *(const float4*)(Bp + k0);
        __syncthreads();
        As[lk + 0][lm] = av.x; As[lk + 1][lm] = av.y;
        As[lk + 2][lm] = av.z; As[lk + 3][lm] = av.w;
        Bs[lk + 0][lm] = bv.x; Bs[lk + 1][lm] = bv.y;
        Bs[lk + 2][lm] = bv.z; Bs[lk + 3][lm] = bv.w;
        __syncthreads();
#pragma unroll
        for (int k = 0; k < BK; k++) {
            float ar[8], br[8];
            *(float4*)&ar[0] = *(const float4*)&As[k][ty * 8];
            *(float4*)&ar[4] = *(const float4*)&As[k][ty * 8 + 4];
            *(float4*)&br[0] = *(const float4*)&Bs[k][tx * 8];
            *(float4*)&br[4] = *(const float4*)&Bs[k][tx * 8 + 4];
#pragma unroll
            for (int i = 0; i < 8; i++)
#pragma unroll
                for (int j = 0; j < 8; j++)
                    acc[i][j] = fmaf(ar[i], br[j], acc[i][j]);
        }
    }
#pragma unroll
    for (int i = 0; i < 8; i++) {
        int m = m0 + ty * 8 + i;
        float* Crow = C + (size_t)m * ldc;
#pragma unroll
        for (int j = 0; j < 8; j++) {
            int n = n0 + tx * 8 + j;
            if (n < N) {
                float v = acc[i][j];
                if (epi == 1) {
                    v += aux[n];
                    v = (v > 20.f) ? v : log1pf(__expf(v));
                } else if (epi == 2) {
                    v += Crow[n];
                }
                Crow[n] = v;
            }
        }
    }
}

// ---------------- split-K reduce ----------------
__global__ void reduce8_k(const float* __restrict__ part, float* __restrict__ out, int n) {
    int i = blockIdx.x * blockDim.x + threadIdx.x;
    if (i >= n) return;
    float s = 0.f;
#pragma unroll
    for (int z = 0; z < KSPLIT; z++) s += part[(size_t)z * n + i];
    out[i] = s;
}

// ---------------- selective scan ----------------
__global__ void scan1_k(const float* __restrict__ delta, const float* __restrict__ xb,
                        const float* __restrict__ dbc, const float* __restrict__ A_log,
                        float* __restrict__ cp, float* __restrict__ cs) {
    int i = blockIdx.x * blockDim.x + threadIdx.x;
    if (i >= NCHUNK * ED) return;
    int c = i / ED, e = i % ED;
    float A[NST], h[NST], p[NST];
#pragma unroll
    for (int n = 0; n < NST; n++) {
        A[n] = -__expf(A_log[e * NST + n]);
        h[n] = 0.f; p[n] = 1.f;
    }
    int t0 = c * CHUNK;
    for (int t = t0; t < t0 + CHUNK; t++) {
        float d  = delta[(size_t)t * ED + e];
        float xv = xb[(size_t)t * ED + e];
        float dx = d * xv;
        const float* Bt = dbc + (size_t)t * DXP + DTR;
#pragma unroll
        for (int n = 0; n < NST; n++) {
            float a = __expf(d * A[n]);
            p[n] *= a;
            h[n] = fmaf(a, h[n], dx * Bt[n]);
        }
    }
    size_t o = (size_t)i * NST;
#pragma unroll
    for (int n = 0; n < NST; n++) { cp[o + n] = p[n]; cs[o + n] = h[n]; }
}

__global__ void carry_k(const float* __restrict__ cp, const float* __restrict__ cs,
                        float* __restrict__ cc) {
    int i = blockIdx.x * blockDim.x + threadIdx.x;
    if (i >= ED * NST) return;
    float H = 0.f;
    for (int c = 0; c < NCHUNK; c++) {
        size_t idx = (size_t)c * ED * NST + i;
        cc[idx] = H;
        H = fmaf(cp[idx], H, cs[idx]);
    }
}

__global__ void scan2_k(const float* __restrict__ delta, const float* __restrict__ xb,
                        const float* __restrict__ dbc, const float* __restrict__ A_log,
                        const float* __restrict__ cc, const float* __restrict__ Dp,
                        const float* __restrict__ xz,
                        __nv_bfloat16* __restrict__ yzh, __nv_bfloat16* __restrict__ yzl) {
    int i = blockIdx.x * blockDim.x + threadIdx.x;
    if (i >= NCHUNK * ED) return;
    int c = i / ED, e = i % ED;
    float A[NST], h[NST];
#pragma unroll
    for (int n = 0; n < NST; n++) {
        A[n] = -__expf(A_log[e * NST + n]);
        h[n] = cc[(size_t)i * NST + n];
    }
    float Dv = Dp[e];
    int t0 = c * CHUNK;
    for (int t = t0; t < t0 + CHUNK; t++) {
        float d  = delta[(size_t)t * ED + e];
        float xv = xb[(size_t)t * ED + e];
        float dx = d * xv;
        const float* Bt = dbc + (size_t)t * DXP + DTR;
        const float* Ct = dbc + (size_t)t * DXP + DTR + NST;
        float y = 0.f;
#pragma unroll
        for (int n = 0; n < NST; n++) {
            float a = __expf(d * A[n]);
            h[n] = fmaf(a, h[n], dx * Bt[n]);
            y = fmaf(h[n], Ct[n], y);
        }
        float zv = xz[(size_t)t * (2 * ED) + ED + e];
        float sz = zv / (1.f + __expf(-zv));
        float v = (y + xv * Dv) * sz;
        __nv_bfloat16 hb = __float2bfloat16(v);
        yzh[(size_t)t * ED + e] = hb;
        yzl[(size_t)t * ED + e] = __float2bfloat16(v - __bfloat162float(hb));
    }
}

// ---------------- host orchestration ----------------
extern "C" void kernel_launch(void* const* d_in, const int* in_sizes, int n_in,
                              void* d_out, int out_size) {
    const int*   tokens  = (const int*)d_in[0];
    const float* emb     = (const float*)d_in[1];
    const float* norm_w  = (const float*)d_in[2];
    const float* in_proj = (const float*)d_in[3];
    const float* conv_w  = (const float*)d_in[4];
    const float* conv_b  = (const float*)d_in[5];
    const float* x_proj  = (const float*)d_in[6];
    const float* dt_w    = (const float*)d_in[7];
    const float* dt_b    = (const float*)d_in[8];
    const float* A_log   = (const float*)d_in[9];
    const float* Dp      = (const float*)d_in[10];
    const float* out_prj = (const float*)d_in[11];
    const float* norm_f  = (const float*)d_in[12];
    const float* lm_head = (const float*)d_in[13];
    float* logits = (float*)d_out;

    float *x, *xz, *xb, *dbc, *delta, *part, *cp, *cs, *cc;
    __nv_bfloat16 *ah, *al, *wh, *wl;
    cudaGetSymbolAddress((void**)&x,     g_x);
    cudaGetSymbolAddress((void**)&xz,    g_xz);
    cudaGetSymbolAddress((void**)&xb,    g_xb);
    cudaGetSymbolAddress((void**)&dbc,   g_dbc);
    cudaGetSymbolAddress((void**)&delta, g_delta);
    cudaGetSymbolAddress((void**)&part,  g_part);
    cudaGetSymbolAddress((void**)&cp,    g_cp);
    cudaGetSymbolAddress((void**)&cs,    g_cs);
    cudaGetSymbolAddress((void**)&cc,    g_cc);
    cudaGetSymbolAddress((void**)&ah,    g_ah);
    cudaGetSymbolAddress((void**)&al,    g_al);
    cudaGetSymbolAddress((void**)&wh,    g_wh);
    cudaGetSymbolAddress((void**)&wl,    g_wl);

    embed_k<<<(L * D + 255) / 256, 256>>>(tokens, emb, x);

    for (int l = 0; l < NL; l++) {
        rmsnorm_split_k<<<L, 256>>>(x, norm_w + l * D, ah, al);

        // convert in_proj weights, then xz = xn @ in_proj^T
        int nwi = 2 * ED * D;
        split4_k<<<(nwi / 4 + 255) / 256, 256>>>(
            (const float4*)(in_proj + (size_t)l * nwi), (__nv_bfloat162*)wh, (__nv_bfloat162*)wl, nwi / 4);
        hgemm_k<0><<<dim3(L / 128, 2 * ED / 128), 256>>>(
            ah, al, wh, wl, xz, D, 2 * ED);

        conv_silu_k<<<(L * ED + 255) / 256, 256>>>(
            xz, conv_w + (size_t)l * ED * DCONV, conv_b + l * ED, xb);

        // dbc = xb @ x_proj^T  (split-K over 8 chunks of 192)
        gemm_k<<<dim3(1, L / BM, KSPLIT), 256>>>(
            xb, x_proj + (size_t)l * DXP * ED, part,
            L, DXP, ED / KSPLIT, ED, ED, DXP, 0, nullptr, ED / KSPLIT);
        reduce8_k<<<(L * DXP + 255) / 256, 256>>>(part, dbc, L * DXP);

        // delta = softplus(dbc[:, :48] @ dt_w^T + dt_b)
        gemm_k<<<dim3(ED / BN, L / BM), 256>>>(
            dbc, dt_w + (size_t)l * ED * DTR, delta,
            L, ED, DTR, DXP, DTR, ED, 1, dt_b + l * ED, 0);

        // selective scan (writes gated output as bf16 hi/lo)
        scan1_k<<<(NCHUNK * ED) / 256, 256>>>(delta, xb, dbc,
                                              A_log + (size_t)l * ED * NST, cp, cs);
        carry_k<<<(ED * NST) / 256, 256>>>(cp, cs, cc);
        scan2_k<<<(NCHUNK * ED) / 256, 256>>>(delta, xb, dbc,
                                              A_log + (size_t)l * ED * NST, cc,
                                              Dp + l * ED, xz, ah, al);

        // convert out_proj weights, then x += yz @ out_proj^T
        int nwo = D * ED;
        split4_k<<<(nwo / 4 + 255) / 256, 256>>>(
            (const float4*)(out_prj + (size_t)l * nwo), (__nv_bfloat162*)wh, (__nv_bfloat162*)wl, nwo / 4);
        hgemm_k<2><<<dim3(L / 128, D / 128), 256>>>(
            ah, al, wh, wl, x, ED, D);
    }

    rmsnorm_split_k<<<L, 256>>>(x, norm_f, ah, al);

    // convert lm_head weights, then logits = xn @ lm_head^T
    int nwl = VOCAB * D;
    split4_k<<<(nwl / 4 + 255) / 256, 256>>>(
        (const float4*)lm_head, (__nv_bfloat162*)wh, (__nv_bfloat162*)wl, nwl / 4);
    hgemm_k<0><<<dim3(L / 128, VOCAB / 128), 256>>>(
        ah, al, wh, wl, logits, D, VOCAB);
}

// round 4
// speedup vs baseline: 2.7384x; 1.6826x over previous
#include <cuda_runtime.h>
#include <cuda_bf16.h>
#include <math.h>
#include <cstdint>

// ---------------- problem constants ----------------
#define L       2048
#define D       768
#define ED      1536
#define NL      4
#define NST     16
#define DTR     48
#define DXP     80
#define VOCAB   32000
#define DCONV   4
#define CHUNK   64
#define NCHUNK  (L / CHUNK)

// ---------------- scratch ----------------
__device__ __align__(256) float g_x    [L * D];
__device__ __align__(256) float g_xz   [L * 2 * ED];
__device__ __align__(256) float g_xb   [L * ED];
__device__ __align__(256) float g_dbc  [L * DXP];
__device__ __align__(256) float g_delta[L * ED];
__device__ __align__(256) float g_cp   [NCHUNK * ED * NST];
__device__ __align__(256) float g_cs   [NCHUNK * ED * NST];
__device__ __align__(256) float g_cc   [NCHUNK * ED * NST];
__device__ __align__(256) __nv_bfloat16 g_ah[L * ED];
__device__ __align__(256) __nv_bfloat16 g_al[L * ED];
__device__ __align__(256) __nv_bfloat16 g_dh[L * 64];
__device__ __align__(256) __nv_bfloat16 g_dl[L * 64];
__device__ __align__(256) __nv_bfloat16 g_wh[VOCAB * D];
__device__ __align__(256) __nv_bfloat16 g_wl[VOCAB * D];

// ---------------- helpers ----------------
__device__ __forceinline__ uint32_t smem_u32(const void* p) {
    uint32_t a;
    asm("{ .reg .u64 t; cvta.to.shared.u64 t, %1; cvt.u32.u64 %0, t; }" : "=r"(a) : "l"(p));
    return a;
}
__device__ __forceinline__ void ldsm4(uint32_t* r, uint32_t addr) {
    asm volatile("ldmatrix.sync.aligned.m8n8.x4.shared.b16 {%0,%1,%2,%3}, [%4];"
                 : "=r"(r[0]), "=r"(r[1]), "=r"(r[2]), "=r"(r[3]) : "r"(addr));
}
__device__ __forceinline__ void ldsm2(uint32_t* r, uint32_t addr) {
    asm volatile("ldmatrix.sync.aligned.m8n8.x2.shared.b16 {%0,%1}, [%2];"
                 : "=r"(r[0]), "=r"(r[1]) : "r"(addr));
}
__device__ __forceinline__ void mma_bf16(float* d, const uint32_t* a, const uint32_t* b) {
    asm volatile(
        "mma.sync.aligned.m16n8k16.row.col.f32.bf16.bf16.f32 "
        "{%0,%1,%2,%3}, {%4,%5,%6,%7}, {%8,%9}, {%0,%1,%2,%3};"
        : "+f"(d[0]), "+f"(d[1]), "+f"(d[2]), "+f"(d[3])
        : "r"(a[0]), "r"(a[1]), "r"(a[2]), "r"(a[3]), "r"(b[0]), "r"(b[1]));
}
__device__ __forceinline__ void cpa16(uint32_t d, const void* s) {
    asm volatile("cp.async.cg.shared.global [%0], [%1], 16;" :: "r"(d), "l"(s));
}
#define CP_COMMIT() asm volatile("cp.async.commit_group;" ::: "memory")
#define CP_WAIT1()  asm volatile("cp.async.wait_group 1;" ::: "memory")

// ---------------- embedding ----------------
__global__ void embed_k(const int* __restrict__ tok, const float* __restrict__ emb,
                        float* __restrict__ x) {
    int i = blockIdx.x * blockDim.x + threadIdx.x;
    if (i >= L * D) return;
    int t = i / D, d = i % D;
    x[i] = emb[(size_t)tok[t] * D + d];
}

// ---------------- fp32 -> bf16 hi/lo split ----------------
__global__ void split4_k(const float4* __restrict__ src, __nv_bfloat162* __restrict__ hi,
                         __nv_bfloat162* __restrict__ lo, int n4) {
    int i = blockIdx.x * blockDim.x + threadIdx.x;
    if (i >= n4) return;
    float4 v = src[i];
    __nv_bfloat16 hx = __float2bfloat16(v.x), hy = __float2bfloat16(v.y);
    __nv_bfloat16 hz = __float2bfloat16(v.z), hw = __float2bfloat16(v.w);
    hi[2 * i]     = __nv_bfloat162(hx, hy);
    hi[2 * i + 1] = __nv_bfloat162(hz, hw);
    lo[2 * i]     = __nv_bfloat162(__float2bfloat16(v.x - __bfloat162float(hx)),
                                   __float2bfloat16(v.y - __bfloat162float(hy)));
    lo[2 * i + 1] = __nv_bfloat162(__float2bfloat16(v.z - __bfloat162float(hz)),
                                   __float2bfloat16(v.w - __bfloat162float(hw)));
}

// padded split: dst [Mdst, Kp], src [Msrc(rows), cols Kin of stride Ssrc]; zero-fill pad
__global__ void split_pad_k(const float* __restrict__ src, __nv_bfloat16* __restrict__ hi,
                            __nv_bfloat16* __restrict__ lo,
                            int Mdst, int Kp, int Msrc, int Kin, int Ssrc) {
    int i = blockIdx.x * blockDim.x + threadIdx.x;
    if (i >= Mdst * Kp) return;
    int r = i / Kp, c = i % Kp;
    float v = (r < Msrc && c < Kin) ? src[(size_t)r * Ssrc + c] : 0.f;
    __nv_bfloat16 h = __float2bfloat16(v);
    hi[i] = h;
    lo[i] = __float2bfloat16(v - __bfloat162float(h));
}

// ---------------- RMSNorm -> bf16 hi/lo ----------------
__global__ void rmsnorm_split_k(const float* __restrict__ x, const float* __restrict__ w,
                                __nv_bfloat16* __restrict__ oh, __nv_bfloat16* __restrict__ ol) {
    int t = blockIdx.x;
    const float* xr = x + (size_t)t * D;
    float s = 0.f;
    for (int d = threadIdx.x; d < D; d += 256) { float v = xr[d]; s += v * v; }
    __shared__ float red[256];
    red[threadIdx.x] = s;
    __syncthreads();
    for (int o = 128; o > 0; o >>= 1) {
        if (threadIdx.x < o) red[threadIdx.x] += red[threadIdx.x + o];
        __syncthreads();
    }
    float inv = rsqrtf(red[0] / (float)D + 1e-5f);
    for (int d = threadIdx.x; d < D; d += 256) {
        float v = xr[d] * inv * w[d];
        __nv_bfloat16 h = __float2bfloat16(v);
        oh[(size_t)t * D + d] = h;
        ol[(size_t)t * D + d] = __float2bfloat16(v - __bfloat162float(h));
    }
}

// ---------------- depthwise causal conv1d + silu ----------------
__global__ void conv_silu_k(const float* __restrict__ xz, const float* __restrict__ w,
                            const float* __restrict__ b, float* __restrict__ xb) {
    int i = blockIdx.x * blockDim.x + threadIdx.x;
    if (i >= L * ED) return;
    int t = i / ED, e = i % ED;
    const float* wr = w + e * DCONV;
    float acc = b[e];
#pragma unroll
    for (int j = 0; j < DCONV; j++) {
        int tt = t - (DCONV - 1) + j;
        if (tt >= 0) acc = fmaf(xz[(size_t)tt * (2 * ED) + e], wr[j], acc);
    }
    xb[i] = acc / (1.f + __expf(-acc));
}

// ---------------- bf16 3-term split GEMM via mma.sync + cp.async ----------------
// C[(MT*32) x 128] tile. C = Ah*Bh^T + Al*Bh^T + Ah*Bl^T (fp32 accum).
// EPI: 0 = store, 1 = softplus(acc + aux[n]), 2 = C += acc.  Nlim guards column stores.
#define ROWB 80

template<int MT, int EPI>
__global__ __launch_bounds__(256, 2) void hgemm_k(
    const __nv_bfloat16* __restrict__ Ah, const __nv_bfloat16* __restrict__ Al,
    const __nv_bfloat16* __restrict__ Bh, const __nv_bfloat16* __restrict__ Bl,
    float* __restrict__ C, int K, int ldc, int Nlim, const float* __restrict__ aux)
{
    constexpr int ASZ   = MT * 32 * ROWB;          // bytes per A array per buffer
    constexpr int BSZ   = 128 * ROWB;              // bytes per B array per buffer
    constexpr int BUFSZ = 2 * ASZ + 2 * BSZ;

    extern __shared__ char dynsm[];
    uint32_t base = smem_u32(dynsm);

    int tid = threadIdx.x, lane = tid & 31, wid = tid >> 5;
    int m0 = blockIdx.x * (MT * 32), n0 = blockIdx.y * 128;
    int wm = (wid & 1) * (MT * 16), wn = (wid >> 1) * 32;

    int lr = tid >> 2;            // 0..63
    int lk = (tid & 3) * 8;       // elem offset within 32-chunk

    const __nv_bfloat16* gAh0 = Ah + (size_t)(m0 + lr) * K + lk;
    const __nv_bfloat16* gAl0 = Al + (size_t)(m0 + lr) * K + lk;
    const __nv_bfloat16* gAh1 = (MT == 4) ? gAh0 + (size_t)64 * K : gAh0;
    const __nv_bfloat16* gAl1 = (MT == 4) ? gAl0 + (size_t)64 * K : gAl0;
    const __nv_bfloat16* gBh0 = Bh + (size_t)(n0 + lr) * K + lk;
    const __nv_bfloat16* gBl0 = Bl + (size_t)(n0 + lr) * K + lk;
    const __nv_bfloat16* gBh1 = gBh0 + (size_t)64 * K;
    const __nv_bfloat16* gBl1 = gBl0 + (size_t)64 * K;

    uint32_t st0 = (uint32_t)(lr * ROWB + lk * 2);
    uint32_t st1 = st0 + 64 * ROWB;

    uint32_t aOff = (uint32_t)((wm + (lane & 15)) * ROWB + (lane >> 4) * 16);
    uint32_t bOff = (uint32_t)((wn + (lane & 7)) * ROWB + ((lane >> 3) & 1) * 16);

    float acc[MT][4][4];
#pragma unroll
    for (int i = 0; i < MT; i++)
#pragma unroll
        for (int j = 0; j < 4; j++)
#pragma unroll
            for (int r = 0; r < 4; r++) acc[i][j][r] = 0.f;

    int nchunk = K >> 5;

    auto prefetch = [&](int kc, int buf) {
        int ko = kc * 32;
        uint32_t bo = base + buf * BUFSZ;
        if (MT == 4) {
            cpa16(bo + st0, gAh0 + ko);        cpa16(bo + st1, gAh1 + ko);
            cpa16(bo + ASZ + st0, gAl0 + ko);  cpa16(bo + ASZ + st1, gAl1 + ko);
        } else if (MT == 2) {
            cpa16(bo + st0, gAh0 + ko);
            cpa16(bo + ASZ + st0, gAl0 + ko);
        } else {
            if (lr < 32) {
                cpa16(bo + st0, gAh0 + ko);
                cpa16(bo + ASZ + st0, gAl0 + ko);
            }
        }
        cpa16(bo + 2 * ASZ + st0, gBh0 + ko);        cpa16(bo + 2 * ASZ + st1, gBh1 + ko);
        cpa16(bo + 2 * ASZ + BSZ + st0, gBl0 + ko);  cpa16(bo + 2 * ASZ + BSZ + st1, gBl1 + ko);
    };

    prefetch(0, 0);
    CP_COMMIT();

    for (int kc = 0; kc < nchunk; kc++) {
        if (kc + 1 < nchunk) prefetch(kc + 1, (kc + 1) & 1);
        CP_COMMIT();
        CP_WAIT1();
        __syncthreads();

        uint32_t bo = base + (kc & 1) * BUFSZ;
#pragma unroll
        for (int kk = 0; kk < 2; kk++) {
            uint32_t kb = kk * 32;
            uint32_t bh[4][2], bl[4][2];
#pragma unroll
            for (int nt = 0; nt < 4; nt++) {
                uint32_t off = bOff + nt * 8 * ROWB + kb;
                ldsm2(bh[nt], bo + 2 * ASZ + off);
                ldsm2(bl[nt], bo + 2 * ASZ + BSZ + off);
            }
#pragma unroll
            for (int mt = 0; mt < MT; mt++) {
                uint32_t off = aOff + mt * 16 * ROWB + kb;
                uint32_t ah[4], al[4];
                ldsm4(ah, bo + off);
                ldsm4(al, bo + ASZ + off);
#pragma unroll
                for (int nt = 0; nt < 4; nt++) {
                    mma_bf16(acc[mt][nt], ah, bh[nt]);
                    mma_bf16(acc[mt][nt], al, bh[nt]);
                    mma_bf16(acc[mt][nt], ah, bl[nt]);
                }
            }
        }
        __syncthreads();
    }

    // epilogue
    int er = m0 + wm + (lane >> 2);
    int ec = n0 + wn + (lane & 3) * 2;
#pragma unroll
    for (int mt = 0; mt < MT; mt++) {
#pragma unroll
        for (int nt = 0; nt < 4; nt++) {
            int col = ec + nt * 8;
            if (col >= Nlim) continue;
            float* p0 = C + (size_t)(er + mt * 16) * ldc + col;
            float* p1 = p0 + 8 * ldc;
            float d0 = acc[mt][nt][0], d1 = acc[mt][nt][1];
            float d2 = acc[mt][nt][2], d3 = acc[mt][nt][3];
            if (EPI == 1) {
                float b0 = aux[col], b1 = aux[col + 1];
                d0 += b0; d1 += b1; d2 += b0; d3 += b1;
                d0 = (d0 > 20.f) ? d0 : log1pf(__expf(d0));
                d1 = (d1 > 20.f) ? d1 : log1pf(__expf(d1));
                d2 = (d2 > 20.f) ? d2 : log1pf(__expf(d2));
                d3 = (d3 > 20.f) ? d3 : log1pf(__expf(d3));
            } else if (EPI == 2) {
                float2 o0 = *(float2*)p0, o1 = *(float2*)p1;
                d0 += o0.x; d1 += o0.y; d2 += o1.x; d3 += o1.y;
            }
            *(float2*)p0 = make_float2(d0, d1);
            *(float2*)p1 = make_float2(d2, d3);
        }
    }
}

// ---------------- selective scan ----------------
__global__ void scan1_k(const float* __restrict__ delta, const float* __restrict__ xb,
                        const float* __restrict__ dbc, const float* __restrict__ A_log,
                        float* __restrict__ cp, float* __restrict__ cs) {
    int i = blockIdx.x * blockDim.x + threadIdx.x;
    if (i >= NCHUNK * ED) return;
    int c = i / ED, e = i % ED;
    float A[NST], h[NST], p[NST];
#pragma unroll
    for (int n = 0; n < NST; n++) {
        A[n] = -__expf(A_log[e * NST + n]);
        h[n] = 0.f; p[n] = 1.f;
    }
    int t0 = c * CHUNK;
    for (int t = t0; t < t0 + CHUNK; t++) {
        float d  = delta[(size_t)t * ED + e];
        float xv = xb[(size_t)t * ED + e];
        float dx = d * xv;
        const float* Bt = dbc + (size_t)t * DXP + DTR;
#pragma unroll
        for (int n = 0; n < NST; n++) {
            float a = __expf(d * A[n]);
            p[n] *= a;
            h[n] = fmaf(a, h[n], dx * Bt[n]);
        }
    }
    size_t o = (size_t)i * NST;
#pragma unroll
    for (int n = 0; n < NST; n++) { cp[o + n] = p[n]; cs[o + n] = h[n]; }
}

__global__ void carry_k(const float* __restrict__ cp, const float* __restrict__ cs,
                        float* __restrict__ cc) {
    int i = blockIdx.x * blockDim.x + threadIdx.x;
    if (i >= ED * NST) return;
    float H = 0.f;
    for (int c = 0; c < NCHUNK; c++) {
        size_t idx = (size_t)c * ED * NST + i;
        cc[idx] = H;
        H = fmaf(cp[idx], H, cs[idx]);
    }
}

__global__ void scan2_k(const float* __restrict__ delta, const float* __restrict__ xb,
                        const float* __restrict__ dbc, const float* __restrict__ A_log,
                        const float* __restrict__ cc, const float* __restrict__ Dp,
                        const float* __restrict__ xz,
                        __nv_bfloat16* __restrict__ yzh, __nv_bfloat16* __restrict__ yzl) {
    int i = blockIdx.x * blockDim.x + threadIdx.x;
    if (i >= NCHUNK * ED) return;
    int c = i / ED, e = i % ED;
    float A[NST], h[NST];
#pragma unroll
    for (int n = 0; n < NST; n++) {
        A[n] = -__expf(A_log[e * NST + n]);
        h[n] = cc[(size_t)i * NST + n];
    }
    float Dv = Dp[e];
    int t0 = c * CHUNK;
    for (int t = t0; t < t0 + CHUNK; t++) {
        float d  = delta[(size_t)t * ED + e];
        float xv = xb[(size_t)t * ED + e];
        float dx = d * xv;
        const float* Bt = dbc + (size_t)t * DXP + DTR;
        const float* Ct = dbc + (size_t)t * DXP + DTR + NST;
        float y = 0.f;
#pragma unroll
        for (int n = 0; n < NST; n++) {
            float a = __expf(d * A[n]);
            h[n] = fmaf(a, h[n], dx * Bt[n]);
            y = fmaf(h[n], Ct[n], y);
        }
        float zv = xz[(size_t)t * (2 * ED) + ED + e];
        float sz = zv / (1.f + __expf(-zv));
        float v = (y + xv * Dv) * sz;
        __nv_bfloat16 hb = __float2bfloat16(v);
        yzh[(size_t)t * ED + e] = hb;
        yzl[(size_t)t * ED + e] = __float2bfloat16(v - __bfloat162float(hb));
    }
}

// ---------------- host orchestration ----------------
extern "C" void kernel_launch(void* const* d_in, const int* in_sizes, int n_in,
                              void* d_out, int out_size) {
    const int*   tokens  = (const int*)d_in[0];
    const float* emb     = (const float*)d_in[1];
    const float* norm_w  = (const float*)d_in[2];
    const float* in_proj = (const float*)d_in[3];
    const float* conv_w  = (const float*)d_in[4];
    const float* conv_b  = (const float*)d_in[5];
    const float* x_proj  = (const float*)d_in[6];
    const float* dt_w    = (const float*)d_in[7];
    const float* dt_b    = (const float*)d_in[8];
    const float* A_log   = (const float*)d_in[9];
    const float* Dp      = (const float*)d_in[10];
    const float* out_prj = (const float*)d_in[11];
    const float* norm_f  = (const float*)d_in[12];
    const float* lm_head = (const float*)d_in[13];
    float* logits = (float*)d_out;

    float *x, *xz, *xb, *dbc, *delta, *cp, *cs, *cc;
    __nv_bfloat16 *ah, *al, *dh, *dl, *wh, *wl;
    cudaGetSymbolAddress((void**)&x,     g_x);
    cudaGetSymbolAddress((void**)&xz,    g_xz);
    cudaGetSymbolAddress((void**)&xb,    g_xb);
    cudaGetSymbolAddress((void**)&dbc,   g_dbc);
    cudaGetSymbolAddress((void**)&delta, g_delta);
    cudaGetSymbolAddress((void**)&cp,    g_cp);
    cudaGetSymbolAddress((void**)&cs,    g_cs);
    cudaGetSymbolAddress((void**)&cc,    g_cc);
    cudaGetSymbolAddress((void**)&ah,    g_ah);
    cudaGetSymbolAddress((void**)&al,    g_al);
    cudaGetSymbolAddress((void**)&dh,    g_dh);
    cudaGetSymbolAddress((void**)&dl,    g_dl);
    cudaGetSymbolAddress((void**)&wh,    g_wh);
    cudaGetSymbolAddress((void**)&wl,    g_wl);

    // dynamic smem sizes per MT (double buffer)
    const int SM4 = 2 * (2 * 4 * 32 * ROWB + 2 * 128 * ROWB);   // 81920
    const int SM2 = 2 * (2 * 2 * 32 * ROWB + 2 * 128 * ROWB);   // 61440
    const int SM1 = 2 * (2 * 1 * 32 * ROWB + 2 * 128 * ROWB);   // 51200
    static bool attr_done = false;
    if (!attr_done) {
        cudaFuncSetAttribute(hgemm_k<2,0>, cudaFuncAttributeMaxDynamicSharedMemorySize, SM2);
        cudaFuncSetAttribute(hgemm_k<2,2>, cudaFuncAttributeMaxDynamicSharedMemorySize, SM2);
        cudaFuncSetAttribute(hgemm_k<1,0>, cudaFuncAttributeMaxDynamicSharedMemorySize, SM1);
        cudaFuncSetAttribute(hgemm_k<4,1>, cudaFuncAttributeMaxDynamicSharedMemorySize, SM4);
        cudaFuncSetAttribute(hgemm_k<4,0>, cudaFuncAttributeMaxDynamicSharedMemorySize, SM4);
        attr_done = true;
    }

    embed_k<<<(L * D + 255) / 256, 256>>>(tokens, emb, x);

    for (int l = 0; l < NL; l++) {
        rmsnorm_split_k<<<L, 256>>>(x, norm_w + l * D, ah, al);

        // xz = xn @ in_proj^T
        int nwi = 2 * ED * D;
        split4_k<<<(nwi / 4 + 255) / 256, 256>>>(
            (const float4*)(in_proj + (size_t)l * nwi), (__nv_bfloat162*)wh, (__nv_bfloat162*)wl, nwi / 4);
        hgemm_k<2,0><<<dim3(L / 64, 2 * ED / 128), 256, SM2>>>(
            ah, al, wh, wl, xz, D, 2 * ED, 2 * ED, nullptr);

        conv_silu_k<<<(L * ED + 255) / 256, 256>>>(
            xz, conv_w + (size_t)l * ED * DCONV, conv_b + l * ED, xb);

        // dbc = xb @ x_proj^T  (N=80 padded to 128)
        split4_k<<<(L * ED / 4 + 255) / 256, 256>>>(
            (const float4*)xb, (__nv_bfloat162*)ah, (__nv_bfloat162*)al, L * ED / 4);
        split_pad_k<<<(128 * ED + 255) / 256, 256>>>(
            x_proj + (size_t)l * DXP * ED, wh, wl, 128, ED, DXP, ED, ED);
        hgemm_k<1,0><<<dim3(L / 32, 1), 256, SM1>>>(
            ah, al, wh, wl, dbc, ED, DXP, DXP, nullptr);

        // delta = softplus(dbc[:, :48] @ dt_w^T + dt_b)   (K=48 padded to 64)
        split_pad_k<<<(L * 64 + 255) / 256, 256>>>(dbc, dh, dl, L, 64, L, DTR, DXP);
        split_pad_k<<<(ED * 64 + 255) / 256, 256>>>(
            dt_w + (size_t)l * ED * DTR, wh, wl, ED, 64, ED, DTR, DTR);
        hgemm_k<4,1><<<dim3(L / 128, ED / 128), 256, SM4>>>(
            dh, dl, wh, wl, delta, 64, ED, ED, dt_b + l * ED);

        // selective scan (writes gated output as bf16 hi/lo into ah/al)
        scan1_k<<<(NCHUNK * ED) / 256, 256>>>(delta, xb, dbc,
                                              A_log + (size_t)l * ED * NST, cp, cs);
        carry_k<<<(ED * NST) / 256, 256>>>(cp, cs, cc);
        scan2_k<<<(NCHUNK * ED) / 256, 256>>>(delta, xb, dbc,
                                              A_log + (size_t)l * ED * NST, cc,
                                              Dp + l * ED, xz, ah, al);

        // x += yz @ out_proj^T
        int nwo = D * ED;
        split4_k<<<(nwo / 4 + 255) / 256, 256>>>(
            (const float4*)(out_prj + (size_t)l * nwo), (__nv_bfloat162*)wh, (__nv_bfloat162*)wl, nwo / 4);
        hgemm_k<2,2><<<dim3(L / 64, D / 128), 256, SM2>>>(
            ah, al, wh, wl, x, ED, D, D, nullptr);
    }

    rmsnorm_split_k<<<L, 256>>>(x, norm_f, ah, al);

    // logits = xn @ lm_head^T
    int nwl = VOCAB * D;
    split4_k<<<(nwl / 4 + 255) / 256, 256>>>(
        (const float4*)lm_head, (__nv_bfloat162*)wh, (__nv_bfloat162*)wl, nwl / 4);
    hgemm_k<4,0><<<dim3(L / 128, VOCAB / 128), 256, SM4>>>(
        ah, al, wh, wl, logits, D, VOCAB, VOCAB, nullptr);
}

// round 5
// speedup vs baseline: 2.7714x; 1.0120x over previous
#include <cuda_runtime.h>
#include <cuda_bf16.h>
#include <math.h>
#include <cstdint>

// ---------------- problem constants ----------------
#define L       2048
#define D       768
#define ED      1536
#define NL      4
#define NST     16
#define DTR     48
#define DXP     80
#define VOCAB   32000
#define DCONV   4
#define CHUNK   64
#define NCHUNK  (L / CHUNK)

// ---------------- scratch ----------------
__device__ __align__(256) float g_x    [L * D];
__device__ __align__(256) float g_xz   [L * 2 * ED];
__device__ __align__(256) float g_xb   [L * ED];
__device__ __align__(256) float g_dbc  [L * DXP];
__device__ __align__(256) float g_delta[L * ED];
__device__ __align__(256) float g_cp   [NCHUNK * ED * NST];
__device__ __align__(256) float g_cs   [NCHUNK * ED * NST];
__device__ __align__(256) float g_cc   [NCHUNK * ED * NST];
__device__ __align__(256) __nv_bfloat16 g_ah[L * ED];
__device__ __align__(256) __nv_bfloat16 g_al[L * ED];
__device__ __align__(256) __nv_bfloat16 g_dh[L * 64];
__device__ __align__(256) __nv_bfloat16 g_dl[L * 64];
__device__ __align__(256) __nv_bfloat16 g_wh[VOCAB * D];
__device__ __align__(256) __nv_bfloat16 g_wl[VOCAB * D];

// ---------------- helpers ----------------
__device__ __forceinline__ uint32_t smem_u32(const void* p) {
    uint32_t a;
    asm("{ .reg .u64 t; cvta.to.shared.u64 t, %1; cvt.u32.u64 %0, t; }" : "=r"(a) : "l"(p));
    return a;
}
__device__ __forceinline__ void ldsm4(uint32_t* r, uint32_t addr) {
    asm volatile("ldmatrix.sync.aligned.m8n8.x4.shared.b16 {%0,%1,%2,%3}, [%4];"
                 : "=r"(r[0]), "=r"(r[1]), "=r"(r[2]), "=r"(r[3]) : "r"(addr));
}
__device__ __forceinline__ void ldsm2(uint32_t* r, uint32_t addr) {
    asm volatile("ldmatrix.sync.aligned.m8n8.x2.shared.b16 {%0,%1}, [%2];"
                 : "=r"(r[0]), "=r"(r[1]) : "r"(addr));
}
__device__ __forceinline__ void mma_bf16(float* d, const uint32_t* a, const uint32_t* b) {
    asm volatile(
        "mma.sync.aligned.m16n8k16.row.col.f32.bf16.bf16.f32 "
        "{%0,%1,%2,%3}, {%4,%5,%6,%7}, {%8,%9}, {%0,%1,%2,%3};"
        : "+f"(d[0]), "+f"(d[1]), "+f"(d[2]), "+f"(d[3])
        : "r"(a[0]), "r"(a[1]), "r"(a[2]), "r"(a[3]), "r"(b[0]), "r"(b[1]));
}
__device__ __forceinline__ void cpa16(uint32_t d, const void* s) {
    asm volatile("cp.async.cg.shared.global [%0], [%1], 16;" :: "r"(d), "l"(s));
}
#define CP_COMMIT() asm volatile("cp.async.commit_group;" ::: "memory")
#define CP_WAIT0()  asm volatile("cp.async.wait_group 0;" ::: "memory")

// ---------------- embedding ----------------
__global__ void embed_k(const int* __restrict__ tok, const float* __restrict__ emb,
                        float* __restrict__ x) {
    int i = blockIdx.x * blockDim.x + threadIdx.x;
    if (i >= L * D) return;
    int t = i / D, d = i % D;
    x[i] = emb[(size_t)tok[t] * D + d];
}

// ---------------- fp32 -> bf16 hi/lo split ----------------
__global__ void split4_k(const float4* __restrict__ src, __nv_bfloat162* __restrict__ hi,
                         __nv_bfloat162* __restrict__ lo, int n4) {
    int i = blockIdx.x * blockDim.x + threadIdx.x;
    if (i >= n4) return;
    float4 v = src[i];
    __nv_bfloat16 hx = __float2bfloat16(v.x), hy = __float2bfloat16(v.y);
    __nv_bfloat16 hz = __float2bfloat16(v.z), hw = __float2bfloat16(v.w);
    hi[2 * i]     = __nv_bfloat162(hx, hy);
    hi[2 * i + 1] = __nv_bfloat162(hz, hw);
    lo[2 * i]     = __nv_bfloat162(__float2bfloat16(v.x - __bfloat162float(hx)),
                                   __float2bfloat16(v.y - __bfloat162float(hy)));
    lo[2 * i + 1] = __nv_bfloat162(__float2bfloat16(v.z - __bfloat162float(hz)),
                                   __float2bfloat16(v.w - __bfloat162float(hw)));
}

// padded split
__global__ void split_pad_k(const float* __restrict__ src, __nv_bfloat16* __restrict__ hi,
                            __nv_bfloat16* __restrict__ lo,
                            int Mdst, int Kp, int Msrc, int Kin, int Ssrc) {
    int i = blockIdx.x * blockDim.x + threadIdx.x;
    if (i >= Mdst * Kp) return;
    int r = i / Kp, c = i % Kp;
    float v = (r < Msrc && c < Kin) ? src[(size_t)r * Ssrc + c] : 0.f;
    __nv_bfloat16 h = __float2bfloat16(v);
    hi[i] = h;
    lo[i] = __float2bfloat16(v - __bfloat162float(h));
}

// ---------------- RMSNorm -> bf16 hi/lo ----------------
__global__ void rmsnorm_split_k(const float* __restrict__ x, const float* __restrict__ w,
                                __nv_bfloat16* __restrict__ oh, __nv_bfloat16* __restrict__ ol) {
    int t = blockIdx.x;
    const float* xr = x + (size_t)t * D;
    float s = 0.f;
    for (int d = threadIdx.x; d < D; d += 256) { float v = xr[d]; s += v * v; }
    __shared__ float red[256];
    red[threadIdx.x] = s;
    __syncthreads();
    for (int o = 128; o > 0; o >>= 1) {
        if (threadIdx.x < o) red[threadIdx.x] += red[threadIdx.x + o];
        __syncthreads();
    }
    float inv = rsqrtf(red[0] / (float)D + 1e-5f);
    for (int d = threadIdx.x; d < D; d += 256) {
        float v = xr[d] * inv * w[d];
        __nv_bfloat16 h = __float2bfloat16(v);
        oh[(size_t)t * D + d] = h;
        ol[(size_t)t * D + d] = __float2bfloat16(v - __bfloat162float(h));
    }
}

// ---------------- conv1d + silu, fused bf16 hi/lo split of output ----------------
__global__ void conv_silu_split_k(const float* __restrict__ xz, const float* __restrict__ w,
                                  const float* __restrict__ b, float* __restrict__ xb,
                                  __nv_bfloat16* __restrict__ oh, __nv_bfloat16* __restrict__ ol) {
    int i = blockIdx.x * blockDim.x + threadIdx.x;
    if (i >= L * ED) return;
    int t = i / ED, e = i % ED;
    const float* wr = w + e * DCONV;
    float acc = b[e];
#pragma unroll
    for (int j = 0; j < DCONV; j++) {
        int tt = t - (DCONV - 1) + j;
        if (tt >= 0) acc = fmaf(xz[(size_t)tt * (2 * ED) + e], wr[j], acc);
    }
    float v = acc / (1.f + __expf(-acc));
    xb[i] = v;
    __nv_bfloat16 h = __float2bfloat16(v);
    oh[i] = h;
    ol[i] = __float2bfloat16(v - __bfloat162float(h));
}

// ---------------- bf16 3-term split GEMM (single-sync double-buffer) ----------------
// C[(MT*32) x 128] tile. C = Ah*Bh^T + Al*Bh^T + Ah*Bl^T (fp32 accum).
// EPI: 0 = store, 1 = softplus(acc + aux[n]), 2 = C += acc.
#define ROWB 80

template<int MT, int EPI>
__global__ __launch_bounds__(256, 2) void hgemm_k(
    const __nv_bfloat16* __restrict__ Ah, const __nv_bfloat16* __restrict__ Al,
    const __nv_bfloat16* __restrict__ Bh, const __nv_bfloat16* __restrict__ Bl,
    float* __restrict__ C, int K, int ldc, int Nlim, const float* __restrict__ aux)
{
    constexpr int ASZ   = MT * 32 * ROWB;
    constexpr int BSZ   = 128 * ROWB;
    constexpr int BUFSZ = 2 * ASZ + 2 * BSZ;

    extern __shared__ char dynsm[];
    uint32_t base = smem_u32(dynsm);

    int tid = threadIdx.x, lane = tid & 31, wid = tid >> 5;
    int m0 = blockIdx.x * (MT * 32), n0 = blockIdx.y * 128;
    int wm = (wid & 1) * (MT * 16), wn = (wid >> 1) * 32;

    int lr = tid >> 2;
    int lk = (tid & 3) * 8;

    const __nv_bfloat16* gAh0 = Ah + (size_t)(m0 + lr) * K + lk;
    const __nv_bfloat16* gAl0 = Al + (size_t)(m0 + lr) * K + lk;
    const __nv_bfloat16* gAh1 = (MT == 4) ? gAh0 + (size_t)64 * K : gAh0;
    const __nv_bfloat16* gAl1 = (MT == 4) ? gAl0 + (size_t)64 * K : gAl0;
    const __nv_bfloat16* gBh0 = Bh + (size_t)(n0 + lr) * K + lk;
    const __nv_bfloat16* gBl0 = Bl + (size_t)(n0 + lr) * K + lk;
    const __nv_bfloat16* gBh1 = gBh0 + (size_t)64 * K;
    const __nv_bfloat16* gBl1 = gBl0 + (size_t)64 * K;

    uint32_t st0 = (uint32_t)(lr * ROWB + lk * 2);
    uint32_t st1 = st0 + 64 * ROWB;

    uint32_t aOff = (uint32_t)((wm + (lane & 15)) * ROWB + (lane >> 4) * 16);
    uint32_t bOff = (uint32_t)((wn + (lane & 7)) * ROWB + ((lane >> 3) & 1) * 16);

    float acc[MT][4][4];
#pragma unroll
    for (int i = 0; i < MT; i++)
#pragma unroll
        for (int j = 0; j < 4; j++)
#pragma unroll
            for (int r = 0; r < 4; r++) acc[i][j][r] = 0.f;

    int nchunk = K >> 5;

    auto prefetch = [&](int kc, int buf) {
        int ko = kc * 32;
        uint32_t bo = base + buf * BUFSZ;
        if (MT == 4) {
            cpa16(bo + st0, gAh0 + ko);        cpa16(bo + st1, gAh1 + ko);
            cpa16(bo + ASZ + st0, gAl0 + ko);  cpa16(bo + ASZ + st1, gAl1 + ko);
        } else if (MT == 2) {
            cpa16(bo + st0, gAh0 + ko);
            cpa16(bo + ASZ + st0, gAl0 + ko);
        } else {
            if (lr < 32) {
                cpa16(bo + st0, gAh0 + ko);
                cpa16(bo + ASZ + st0, gAl0 + ko);
            }
        }
        cpa16(bo + 2 * ASZ + st0, gBh0 + ko);        cpa16(bo + 2 * ASZ + st1, gBh1 + ko);
        cpa16(bo + 2 * ASZ + BSZ + st0, gBl0 + ko);  cpa16(bo + 2 * ASZ + BSZ + st1, gBl1 + ko);
    };

    prefetch(0, 0);
    CP_COMMIT();

    for (int kc = 0; kc < nchunk; kc++) {
        CP_WAIT0();             // stage kc resident
        __syncthreads();        // publishes stage kc; proves prior readers of (kc+1)&1 done
        if (kc + 1 < nchunk) prefetch(kc + 1, (kc + 1) & 1);
        CP_COMMIT();

        uint32_t bo = base + (kc & 1) * BUFSZ;
#pragma unroll
        for (int kk = 0; kk < 2; kk++) {
            uint32_t kb = kk * 32;
            uint32_t bh[4][2], bl[4][2];
#pragma unroll
            for (int nt = 0; nt < 4; nt++) {
                uint32_t off = bOff + nt * 8 * ROWB + kb;
                ldsm2(bh[nt], bo + 2 * ASZ + off);
                ldsm2(bl[nt], bo + 2 * ASZ + BSZ + off);
            }
            // term 1: Ah * Bh
#pragma unroll
            for (int mt = 0; mt < MT; mt++) {
                uint32_t a[4];
                ldsm4(a, bo + aOff + mt * 16 * ROWB + kb);
#pragma unroll
                for (int nt = 0; nt < 4; nt++) mma_bf16(acc[mt][nt], a, bh[nt]);
            }
            // term 2: Al * Bh
#pragma unroll
            for (int mt = 0; mt < MT; mt++) {
                uint32_t a[4];
                ldsm4(a, bo + ASZ + aOff + mt * 16 * ROWB + kb);
#pragma unroll
                for (int nt = 0; nt < 4; nt++) mma_bf16(acc[mt][nt], a, bh[nt]);
            }
            // term 3: Ah * Bl
#pragma unroll
            for (int mt = 0; mt < MT; mt++) {
                uint32_t a[4];
                ldsm4(a, bo + aOff + mt * 16 * ROWB + kb);
#pragma unroll
                for (int nt = 0; nt < 4; nt++) mma_bf16(acc[mt][nt], a, bl[nt]);
            }
        }
    }

    // epilogue
    int er = m0 + wm + (lane >> 2);
    int ec = n0 + wn + (lane & 3) * 2;
#pragma unroll
    for (int mt = 0; mt < MT; mt++) {
#pragma unroll
        for (int nt = 0; nt < 4; nt++) {
            int col = ec + nt * 8;
            if (col >= Nlim) continue;
            float* p0 = C + (size_t)(er + mt * 16) * ldc + col;
            float* p1 = p0 + 8 * ldc;
            float d0 = acc[mt][nt][0], d1 = acc[mt][nt][1];
            float d2 = acc[mt][nt][2], d3 = acc[mt][nt][3];
            if (EPI == 1) {
                float b0 = aux[col], b1 = aux[col + 1];
                d0 += b0; d1 += b1; d2 += b0; d3 += b1;
                d0 = (d0 > 20.f) ? d0 : log1pf(__expf(d0));
                d1 = (d1 > 20.f) ? d1 : log1pf(__expf(d1));
                d2 = (d2 > 20.f) ? d2 : log1pf(__expf(d2));
                d3 = (d3 > 20.f) ? d3 : log1pf(__expf(d3));
            } else if (EPI == 2) {
                float2 o0 = *(float2*)p0, o1 = *(float2*)p1;
                d0 += o0.x; d1 += o0.y; d2 += o1.x; d3 += o1.y;
            }
            *(float2*)p0 = make_float2(d0, d1);
            *(float2*)p1 = make_float2(d2, d3);
        }
    }
}

// ---------------- selective scan ----------------
__global__ void scan1_k(const float* __restrict__ delta, const float* __restrict__ xb,
                        const float* __restrict__ dbc, const float* __restrict__ A_log,
                        float* __restrict__ cp, float* __restrict__ cs) {
    int i = blockIdx.x * blockDim.x + threadIdx.x;
    if (i >= NCHUNK * ED) return;
    int c = i / ED, e = i % ED;
    float A[NST], h[NST], p[NST];
#pragma unroll
    for (int n = 0; n < NST; n++) {
        A[n] = -__expf(A_log[e * NST + n]);
        h[n] = 0.f; p[n] = 1.f;
    }
    int t0 = c * CHUNK;
    for (int t = t0; t < t0 + CHUNK; t++) {
        float d  = delta[(size_t)t * ED + e];
        float xv = xb[(size_t)t * ED + e];
        float dx = d * xv;
        const float* Bt = dbc + (size_t)t * DXP + DTR;
#pragma unroll
        for (int n = 0; n < NST; n++) {
            float a = __expf(d * A[n]);
            p[n] *= a;
            h[n] = fmaf(a, h[n], dx * Bt[n]);
        }
    }
    size_t o = (size_t)i * NST;
#pragma unroll
    for (int n = 0; n < NST; n++) { cp[o + n] = p[n]; cs[o + n] = h[n]; }
}

__global__ void carry_k(const float* __restrict__ cp, const float* __restrict__ cs,
                        float* __restrict__ cc) {
    int i = blockIdx.x * blockDim.x + threadIdx.x;
    if (i >= ED * NST) return;
    float H = 0.f;
    for (int c = 0; c < NCHUNK; c++) {
        size_t idx = (size_t)c * ED * NST + i;
        cc[idx] = H;
        H = fmaf(cp[idx], H, cs[idx]);
    }
}

__global__ void scan2_k(const float* __restrict__ delta, const float* __restrict__ xb,
                        const float* __restrict__ dbc, const float* __restrict__ A_log,
                        const float* __restrict__ cc, const float* __restrict__ Dp,
                        const float* __restrict__ xz,
                        __nv_bfloat16* __restrict__ yzh, __nv_bfloat16* __restrict__ yzl) {
    int i = blockIdx.x * blockDim.x + threadIdx.x;
    if (i >= NCHUNK * ED) return;
    int c = i / ED, e = i % ED;
    float A[NST], h[NST];
#pragma unroll
    for (int n = 0; n < NST; n++) {
        A[n] = -__expf(A_log[e * NST + n]);
        h[n] = cc[(size_t)i * NST + n];
    }
    float Dv = Dp[e];
    int t0 = c * CHUNK;
    for (int t = t0; t < t0 + CHUNK; t++) {
        float d  = delta[(size_t)t * ED + e];
        float xv = xb[(size_t)t * ED + e];
        float dx = d * xv;
        const float* Bt = dbc + (size_t)t * DXP + DTR;
        const float* Ct = dbc + (size_t)t * DXP + DTR + NST;
        float y = 0.f;
#pragma unroll
        for (int n = 0; n < NST; n++) {
            float a = __expf(d * A[n]);
            h[n] = fmaf(a, h[n], dx * Bt[n]);
            y = fmaf(h[n], Ct[n], y);
        }
        float zv = xz[(size_t)t * (2 * ED) + ED + e];
        float sz = zv / (1.f + __expf(-zv));
        float v = (y + xv * Dv) * sz;
        __nv_bfloat16 hb = __float2bfloat16(v);
        yzh[(size_t)t * ED + e] = hb;
        yzl[(size_t)t * ED + e] = __float2bfloat16(v - __bfloat162float(hb));
    }
}

// ---------------- host orchestration ----------------
extern "C" void kernel_launch(void* const* d_in, const int* in_sizes, int n_in,
                              void* d_out, int out_size) {
    const int*   tokens  = (const int*)d_in[0];
    const float* emb     = (const float*)d_in[1];
    const float* norm_w  = (const float*)d_in[2];
    const float* in_proj = (const float*)d_in[3];
    const float* conv_w  = (const float*)d_in[4];
    const float* conv_b  = (const float*)d_in[5];
    const float* x_proj  = (const float*)d_in[6];
    const float* dt_w    = (const float*)d_in[7];
    const float* dt_b    = (const float*)d_in[8];
    const float* A_log   = (const float*)d_in[9];
    const float* Dp      = (const float*)d_in[10];
    const float* out_prj = (const float*)d_in[11];
    const float* norm_f  = (const float*)d_in[12];
    const float* lm_head = (const float*)d_in[13];
    float* logits = (float*)d_out;

    float *x, *xz, *xb, *dbc, *delta, *cp, *cs, *cc;
    __nv_bfloat16 *ah, *al, *dh, *dl, *wh, *wl;
    cudaGetSymbolAddress((void**)&x,     g_x);
    cudaGetSymbolAddress((void**)&xz,    g_xz);
    cudaGetSymbolAddress((void**)&xb,    g_xb);
    cudaGetSymbolAddress((void**)&dbc,   g_dbc);
    cudaGetSymbolAddress((void**)&delta, g_delta);
    cudaGetSymbolAddress((void**)&cp,    g_cp);
    cudaGetSymbolAddress((void**)&cs,    g_cs);
    cudaGetSymbolAddress((void**)&cc,    g_cc);
    cudaGetSymbolAddress((void**)&ah,    g_ah);
    cudaGetSymbolAddress((void**)&al,    g_al);
    cudaGetSymbolAddress((void**)&dh,    g_dh);
    cudaGetSymbolAddress((void**)&dl,    g_dl);
    cudaGetSymbolAddress((void**)&wh,    g_wh);
    cudaGetSymbolAddress((void**)&wl,    g_wl);

    const int SM4 = 2 * (2 * 4 * 32 * ROWB + 2 * 128 * ROWB);   // 81920
    const int SM2 = 2 * (2 * 2 * 32 * ROWB + 2 * 128 * ROWB);   // 61440
    const int SM1 = 2 * (2 * 1 * 32 * ROWB + 2 * 128 * ROWB);   // 51200
    static bool attr_done = false;
    if (!attr_done) {
        cudaFuncSetAttribute(hgemm_k<2,0>, cudaFuncAttributeMaxDynamicSharedMemorySize, SM2);
        cudaFuncSetAttribute(hgemm_k<2,2>, cudaFuncAttributeMaxDynamicSharedMemorySize, SM2);
        cudaFuncSetAttribute(hgemm_k<1,0>, cudaFuncAttributeMaxDynamicSharedMemorySize, SM1);
        cudaFuncSetAttribute(hgemm_k<4,1>, cudaFuncAttributeMaxDynamicSharedMemorySize, SM4);
        cudaFuncSetAttribute(hgemm_k<4,0>, cudaFuncAttributeMaxDynamicSharedMemorySize, SM4);
        attr_done = true;
    }

    embed_k<<<(L * D + 255) / 256, 256>>>(tokens, emb, x);

    for (int l = 0; l < NL; l++) {
        rmsnorm_split_k<<<L, 256>>>(x, norm_w + l * D, ah, al);

        // xz = xn @ in_proj^T
        int nwi = 2 * ED * D;
        split4_k<<<(nwi / 4 + 255) / 256, 256>>>(
            (const float4*)(in_proj + (size_t)l * nwi), (__nv_bfloat162*)wh, (__nv_bfloat162*)wl, nwi / 4);
        hgemm_k<2,0><<<dim3(L / 64, 2 * ED / 128), 256, SM2>>>(
            ah, al, wh, wl, xz, D, 2 * ED, 2 * ED, nullptr);

        // conv + silu (also emits bf16 hi/lo of xb into ah/al)
        conv_silu_split_k<<<(L * ED + 255) / 256, 256>>>(
            xz, conv_w + (size_t)l * ED * DCONV, conv_b + l * ED, xb, ah, al);

        // dbc = xb @ x_proj^T  (N=80 padded to 128)
        split_pad_k<<<(128 * ED + 255) / 256, 256>>>(
            x_proj + (size_t)l * DXP * ED, wh, wl, 128, ED, DXP, ED, ED);
        hgemm_k<1,0><<<dim3(L / 32, 1), 256, SM1>>>(
            ah, al, wh, wl, dbc, ED, DXP, DXP, nullptr);

        // delta = softplus(dbc[:, :48] @ dt_w^T + dt_b)   (K=48 padded to 64)
        split_pad_k<<<(L * 64 + 255) / 256, 256>>>(dbc, dh, dl, L, 64, L, DTR, DXP);
        split_pad_k<<<(ED * 64 + 255) / 256, 256>>>(
            dt_w + (size_t)l * ED * DTR, wh, wl, ED, 64, ED, DTR, DTR);
        hgemm_k<4,1><<<dim3(L / 128, ED / 128), 256, SM4>>>(
            dh, dl, wh, wl, delta, 64, ED, ED, dt_b + l * ED);

        // selective scan (writes gated output as bf16 hi/lo into ah/al)
        scan1_k<<<(NCHUNK * ED) / 256, 256>>>(delta, xb, dbc,
                                              A_log + (size_t)l * ED * NST, cp, cs);
        carry_k<<<(ED * NST) / 256, 256>>>(cp, cs, cc);
        scan2_k<<<(NCHUNK * ED) / 256, 256>>>(delta, xb, dbc,
                                              A_log + (size_t)l * ED * NST, cc,
                                              Dp + l * ED, xz, ah, al);

        // x += yz @ out_proj^T
        int nwo = D * ED;
        split4_k<<<(nwo / 4 + 255) / 256, 256>>>(
            (const float4*)(out_prj + (size_t)l * nwo), (__nv_bfloat162*)wh, (__nv_bfloat162*)wl, nwo / 4);
        hgemm_k<2,2><<<dim3(L / 64, D / 128), 256, SM2>>>(
            ah, al, wh, wl, x, ED, D, D, nullptr);
    }

    rmsnorm_split_k<<<L, 256>>>(x, norm_f, ah, al);

    // logits = xn @ lm_head^T
    int nwl = VOCAB * D;
    split4_k<<<(nwl / 4 + 255) / 256, 256>>>(
        (const float4*)lm_head, (__nv_bfloat162*)wh, (__nv_bfloat162*)wl, nwl / 4);
    hgemm_k<4,0><<<dim3(L / 128, VOCAB / 128), 256, SM4>>>(
        ah, al, wh, wl, logits, D, VOCAB, VOCAB, nullptr);
}

// round 6
// speedup vs baseline: 2.7938x; 1.0081x over previous
#include <cuda_runtime.h>
#include <cuda_bf16.h>
#include <math.h>
#include <cstdint>

// ---------------- problem constants ----------------
#define L       2048
#define D       768
#define ED      1536
#define NL      4
#define NST     16
#define DTR     48
#define DXP     80
#define VOCAB   32000
#define DCONV   4
#define CHUNK   64
#define NCHUNK  (L / CHUNK)

// ---------------- scratch ----------------
__device__ __align__(256) float g_x    [L * D];
__device__ __align__(256) float g_xz   [L * 2 * ED];
__device__ __align__(256) float g_xb   [L * ED];
__device__ __align__(256) float g_dbc  [L * DXP];
__device__ __align__(256) float g_delta[L * ED];
__device__ __align__(256) float g_cp   [NCHUNK * ED * NST];
__device__ __align__(256) float g_cs   [NCHUNK * ED * NST];
__device__ __align__(256) float g_cc   [NCHUNK * ED * NST];
__device__ __align__(256) __nv_bfloat16 g_ah[L * ED];
__device__ __align__(256) __nv_bfloat16 g_al[L * ED];
__device__ __align__(256) __nv_bfloat16 g_dh[L * 64];
__device__ __align__(256) __nv_bfloat16 g_dl[L * 64];
__device__ __align__(256) __nv_bfloat16 g_wh[VOCAB * D];
__device__ __align__(256) __nv_bfloat16 g_wl[VOCAB * D];

// ---------------- helpers ----------------
__device__ __forceinline__ uint32_t smem_u32(const void* p) {
    uint32_t a;
    asm("{ .reg .u64 t; cvta.to.shared.u64 t, %1; cvt.u32.u64 %0, t; }" : "=r"(a) : "l"(p));
    return a;
}
__device__ __forceinline__ void ldsm4(uint32_t* r, uint32_t addr) {
    asm volatile("ldmatrix.sync.aligned.m8n8.x4.shared.b16 {%0,%1,%2,%3}, [%4];"
                 : "=r"(r[0]), "=r"(r[1]), "=r"(r[2]), "=r"(r[3]) : "r"(addr));
}
__device__ __forceinline__ void mma_bf16(float* d, const uint32_t* a, const uint32_t* b) {
    asm volatile(
        "mma.sync.aligned.m16n8k16.row.col.f32.bf16.bf16.f32 "
        "{%0,%1,%2,%3}, {%4,%5,%6,%7}, {%8,%9}, {%0,%1,%2,%3};"
        : "+f"(d[0]), "+f"(d[1]), "+f"(d[2]), "+f"(d[3])
        : "r"(a[0]), "r"(a[1]), "r"(a[2]), "r"(a[3]), "r"(b[0]), "r"(b[1]));
}
__device__ __forceinline__ void cpa16(uint32_t d, const void* s) {
    asm volatile("cp.async.cg.shared.global [%0], [%1], 16;" :: "r"(d), "l"(s));
}
#define CP_COMMIT() asm volatile("cp.async.commit_group;" ::: "memory")
#define CP_WAIT0()  asm volatile("cp.async.wait_group 0;" ::: "memory")

// ---------------- embedding ----------------
__global__ void embed_k(const int* __restrict__ tok, const float* __restrict__ emb,
                        float* __restrict__ x) {
    int i = blockIdx.x * blockDim.x + threadIdx.x;
    if (i >= L * D) return;
    int t = i / D, d = i % D;
    x[i] = emb[(size_t)tok[t] * D + d];
}

// ---------------- fp32 -> bf16 hi/lo split ----------------
__global__ void split4_k(const float4* __restrict__ src, __nv_bfloat162* __restrict__ hi,
                         __nv_bfloat162* __restrict__ lo, int n4) {
    int i = blockIdx.x * blockDim.x + threadIdx.x;
    if (i >= n4) return;
    float4 v = src[i];
    __nv_bfloat16 hx = __float2bfloat16(v.x), hy = __float2bfloat16(v.y);
    __nv_bfloat16 hz = __float2bfloat16(v.z), hw = __float2bfloat16(v.w);
    hi[2 * i]     = __nv_bfloat162(hx, hy);
    hi[2 * i + 1] = __nv_bfloat162(hz, hw);
    lo[2 * i]     = __nv_bfloat162(__float2bfloat16(v.x - __bfloat162float(hx)),
                                   __float2bfloat16(v.y - __bfloat162float(hy)));
    lo[2 * i + 1] = __nv_bfloat162(__float2bfloat16(v.z - __bfloat162float(hz)),
                                   __float2bfloat16(v.w - __bfloat162float(hw)));
}

// padded split
__global__ void split_pad_k(const float* __restrict__ src, __nv_bfloat16* __restrict__ hi,
                            __nv_bfloat16* __restrict__ lo,
                            int Mdst, int Kp, int Msrc, int Kin, int Ssrc) {
    int i = blockIdx.x * blockDim.x + threadIdx.x;
    if (i >= Mdst * Kp) return;
    int r = i / Kp, c = i % Kp;
    float v = (r < Msrc && c < Kin) ? src[(size_t)r * Ssrc + c] : 0.f;
    __nv_bfloat16 h = __float2bfloat16(v);
    hi[i] = h;
    lo[i] = __float2bfloat16(v - __bfloat162float(h));
}

// ---------------- RMSNorm -> bf16 hi/lo ----------------
__global__ void rmsnorm_split_k(const float* __restrict__ x, const float* __restrict__ w,
                                __nv_bfloat16* __restrict__ oh, __nv_bfloat16* __restrict__ ol) {
    int t = blockIdx.x;
    const float* xr = x + (size_t)t * D;
    float s = 0.f;
    for (int d = threadIdx.x; d < D; d += 256) { float v = xr[d]; s += v * v; }
    __shared__ float red[256];
    red[threadIdx.x] = s;
    __syncthreads();
    for (int o = 128; o > 0; o >>= 1) {
        if (threadIdx.x < o) red[threadIdx.x] += red[threadIdx.x + o];
        __syncthreads();
    }
    float inv = rsqrtf(red[0] / (float)D + 1e-5f);
    for (int d = threadIdx.x; d < D; d += 256) {
        float v = xr[d] * inv * w[d];
        __nv_bfloat16 h = __float2bfloat16(v);
        oh[(size_t)t * D + d] = h;
        ol[(size_t)t * D + d] = __float2bfloat16(v - __bfloat162float(h));
    }
}

// ---------------- conv1d + silu, fused bf16 hi/lo split of output ----------------
__global__ void conv_silu_split_k(const float* __restrict__ xz, const float* __restrict__ w,
                                  const float* __restrict__ b, float* __restrict__ xb,
                                  __nv_bfloat16* __restrict__ oh, __nv_bfloat16* __restrict__ ol) {
    int i = blockIdx.x * blockDim.x + threadIdx.x;
    if (i >= L * ED) return;
    int t = i / ED, e = i % ED;
    const float* wr = w + e * DCONV;
    float acc = b[e];
#pragma unroll
    for (int j = 0; j < DCONV; j++) {
        int tt = t - (DCONV - 1) + j;
        if (tt >= 0) acc = fmaf(xz[(size_t)tt * (2 * ED) + e], wr[j], acc);
    }
    float v = acc / (1.f + __expf(-acc));
    xb[i] = v;
    __nv_bfloat16 h = __float2bfloat16(v);
    oh[i] = h;
    ol[i] = __float2bfloat16(v - __bfloat162float(h));
}

// ---------------- bf16 3-term split GEMM ----------------
// C[(MT*32) x 128] tile. C = Ah*Bh^T + Al*Bh^T + Ah*Bl^T (fp32 accum).
// EPI: 0 = store, 1 = softplus(acc + aux[n]), 2 = C += acc.
#define ROWB 80

template<int MT, int EPI>
__global__ __launch_bounds__(256, 2) void hgemm_k(
    const __nv_bfloat16* __restrict__ Ah, const __nv_bfloat16* __restrict__ Al,
    const __nv_bfloat16* __restrict__ Bh, const __nv_bfloat16* __restrict__ Bl,
    float* __restrict__ C, int K, int ldc, int Nlim, const float* __restrict__ aux)
{
    constexpr int ASZ   = MT * 32 * ROWB;
    constexpr int BSZ   = 128 * ROWB;
    constexpr int BUFSZ = 2 * ASZ + 2 * BSZ;

    extern __shared__ char dynsm[];
    uint32_t base = smem_u32(dynsm);

    int tid = threadIdx.x, lane = tid & 31, wid = tid >> 5;
    int m0 = blockIdx.x * (MT * 32), n0 = blockIdx.y * 128;
    int wm = (wid & 1) * (MT * 16), wn = (wid >> 1) * 32;

    int lr = tid >> 2;
    int lk = (tid & 3) * 8;

    const __nv_bfloat16* gAh0 = Ah + (size_t)(m0 + lr) * K + lk;
    const __nv_bfloat16* gAl0 = Al + (size_t)(m0 + lr) * K + lk;
    const __nv_bfloat16* gAh1 = (MT == 4) ? gAh0 + (size_t)64 * K : gAh0;
    const __nv_bfloat16* gAl1 = (MT == 4) ? gAl0 + (size_t)64 * K : gAl0;
    const __nv_bfloat16* gBh0 = Bh + (size_t)(n0 + lr) * K + lk;
    const __nv_bfloat16* gBl0 = Bl + (size_t)(n0 + lr) * K + lk;
    const __nv_bfloat16* gBh1 = gBh0 + (size_t)64 * K;
    const __nv_bfloat16* gBl1 = gBl0 + (size_t)64 * K;

    uint32_t st0 = (uint32_t)(lr * ROWB + lk * 2);
    uint32_t st1 = st0 + 64 * ROWB;

    // A frag addresses (x4: 16 rows x 16 k)
    uint32_t aOff = (uint32_t)((wm + (lane & 15)) * ROWB + (lane >> 4) * 16);
    // B frag addresses (x4 covering two nt tiles: 16 n-rows x 16 k)
    uint32_t bOff4 = (uint32_t)((wn + ((lane >> 4) << 3) + (lane & 7)) * ROWB
                                + ((lane >> 3) & 1) * 16);

    float acc[MT][4][4];
#pragma unroll
    for (int i = 0; i < MT; i++)
#pragma unroll
        for (int j = 0; j < 4; j++)
#pragma unroll
            for (int r = 0; r < 4; r++) acc[i][j][r] = 0.f;

    int nchunk = K >> 5;

    auto prefetch = [&](int kc, int buf) {
        int ko = kc * 32;
        uint32_t bo = base + buf * BUFSZ;
        if (MT == 4) {
            cpa16(bo + st0, gAh0 + ko);        cpa16(bo + st1, gAh1 + ko);
            cpa16(bo + ASZ + st0, gAl0 + ko);  cpa16(bo + ASZ + st1, gAl1 + ko);
        } else if (MT == 2) {
            cpa16(bo + st0, gAh0 + ko);
            cpa16(bo + ASZ + st0, gAl0 + ko);
        } else {
            if (lr < 32) {
                cpa16(bo + st0, gAh0 + ko);
                cpa16(bo + ASZ + st0, gAl0 + ko);
            }
        }
        cpa16(bo + 2 * ASZ + st0, gBh0 + ko);        cpa16(bo + 2 * ASZ + st1, gBh1 + ko);
        cpa16(bo + 2 * ASZ + BSZ + st0, gBl0 + ko);  cpa16(bo + 2 * ASZ + BSZ + st1, gBl1 + ko);
    };

    prefetch(0, 0);
    CP_COMMIT();

    for (int kc = 0; kc < nchunk; kc++) {
        CP_WAIT0();
        __syncthreads();
        if (kc + 1 < nchunk) prefetch(kc + 1, (kc + 1) & 1);
        CP_COMMIT();

        uint32_t bo = base + (kc & 1) * BUFSZ;
#pragma unroll
        for (int kk = 0; kk < 2; kk++) {
            uint32_t kb = kk * 32;
            // B fragments: x4 per nt-pair (p=0 -> nt 0,1 ; p=1 -> nt 2,3)
            uint32_t bh4[2][4], bl4[2][4];
#pragma unroll
            for (int p = 0; p < 2; p++) {
                uint32_t off = bOff4 + p * 16 * ROWB + kb;
                ldsm4(bh4[p], bo + 2 * ASZ + off);
                ldsm4(bl4[p], bo + 2 * ASZ + BSZ + off);
            }
            // Ah terms: reuse ah frag for both Bh and Bl
#pragma unroll
            for (int mt = 0; mt < MT; mt++) {
                uint32_t ah[4];
                ldsm4(ah, bo + aOff + mt * 16 * ROWB + kb);
#pragma unroll
                for (int nt = 0; nt < 4; nt++)
                    mma_bf16(acc[mt][nt], ah, &bh4[nt >> 1][(nt & 1) * 2]);
#pragma unroll
                for (int nt = 0; nt < 4; nt++)
                    mma_bf16(acc[mt][nt], ah, &bl4[nt >> 1][(nt & 1) * 2]);
            }
            // Al term
#pragma unroll
            for (int mt = 0; mt < MT; mt++) {
                uint32_t al[4];
                ldsm4(al, bo + ASZ + aOff + mt * 16 * ROWB + kb);
#pragma unroll
                for (int nt = 0; nt < 4; nt++)
                    mma_bf16(acc[mt][nt], al, &bh4[nt >> 1][(nt & 1) * 2]);
            }
        }
    }

    // epilogue
    int er = m0 + wm + (lane >> 2);
    int ec = n0 + wn + (lane & 3) * 2;
#pragma unroll
    for (int mt = 0; mt < MT; mt++) {
#pragma unroll
        for (int nt = 0; nt < 4; nt++) {
            int col = ec + nt * 8;
            if (col >= Nlim) continue;
            float* p0 = C + (size_t)(er + mt * 16) * ldc + col;
            float* p1 = p0 + 8 * ldc;
            float d0 = acc[mt][nt][0], d1 = acc[mt][nt][1];
            float d2 = acc[mt][nt][2], d3 = acc[mt][nt][3];
            if (EPI == 1) {
                float b0 = aux[col], b1 = aux[col + 1];
                d0 += b0; d1 += b1; d2 += b0; d3 += b1;
                d0 = (d0 > 20.f) ? d0 : log1pf(__expf(d0));
                d1 = (d1 > 20.f) ? d1 : log1pf(__expf(d1));
                d2 = (d2 > 20.f) ? d2 : log1pf(__expf(d2));
                d3 = (d3 > 20.f) ? d3 : log1pf(__expf(d3));
            } else if (EPI == 2) {
                float2 o0 = *(float2*)p0, o1 = *(float2*)p1;
                d0 += o0.x; d1 += o0.y; d2 += o1.x; d3 += o1.y;
            }
            *(float2*)p0 = make_float2(d0, d1);
            *(float2*)p1 = make_float2(d2, d3);
        }
    }
}

// ---------------- selective scan ----------------
__global__ void scan1_k(const float* __restrict__ delta, const float* __restrict__ xb,
                        const float* __restrict__ dbc, const float* __restrict__ A_log,
                        float* __restrict__ cp, float* __restrict__ cs) {
    int i = blockIdx.x * blockDim.x + threadIdx.x;
    if (i >= NCHUNK * ED) return;
    int c = i / ED, e = i % ED;
    float A[NST], h[NST], p[NST];
#pragma unroll
    for (int n = 0; n < NST; n++) {
        A[n] = -__expf(A_log[e * NST + n]);
        h[n] = 0.f; p[n] = 1.f;
    }
    int t0 = c * CHUNK;
    for (int t = t0; t < t0 + CHUNK; t++) {
        float d  = delta[(size_t)t * ED + e];
        float xv = xb[(size_t)t * ED + e];
        float dx = d * xv;
        const float* Bt = dbc + (size_t)t * DXP + DTR;
#pragma unroll
        for (int n = 0; n < NST; n++) {
            float a = __expf(d * A[n]);
            p[n] *= a;
            h[n] = fmaf(a, h[n], dx * Bt[n]);
        }
    }
    size_t o = (size_t)i * NST;
#pragma unroll
    for (int n = 0; n < NST; n++) { cp[o + n] = p[n]; cs[o + n] = h[n]; }
}

__global__ void carry_k(const float* __restrict__ cp, const float* __restrict__ cs,
                        float* __restrict__ cc) {
    int i = blockIdx.x * blockDim.x + threadIdx.x;
    if (i >= ED * NST) return;
    float H = 0.f;
    for (int c = 0; c < NCHUNK; c++) {
        size_t idx = (size_t)c * ED * NST + i;
        cc[idx] = H;
        H = fmaf(cp[idx], H, cs[idx]);
    }
}

__global__ void scan2_k(const float* __restrict__ delta, const float* __restrict__ xb,
                        const float* __restrict__ dbc, const float* __restrict__ A_log,
                        const float* __restrict__ cc, const float* __restrict__ Dp,
                        const float* __restrict__ xz,
                        __nv_bfloat16* __restrict__ yzh, __nv_bfloat16* __restrict__ yzl) {
    int i = blockIdx.x * blockDim.x + threadIdx.x;
    if (i >= NCHUNK * ED) return;
    int c = i / ED, e = i % ED;
    float A[NST], h[NST];
#pragma unroll
    for (int n = 0; n < NST; n++) {
        A[n] = -__expf(A_log[e * NST + n]);
        h[n] = cc[(size_t)i * NST + n];
    }
    float Dv = Dp[e];
    int t0 = c * CHUNK;
    for (int t = t0; t < t0 + CHUNK; t++) {
        float d  = delta[(size_t)t * ED + e];
        float xv = xb[(size_t)t * ED + e];
        float dx = d * xv;
        const float* Bt = dbc + (size_t)t * DXP + DTR;
        const float* Ct = dbc + (size_t)t * DXP + DTR + NST;
        float y = 0.f;
#pragma unroll
        for (int n = 0; n < NST; n++) {
            float a = __expf(d * A[n]);
            h[n] = fmaf(a, h[n], dx * Bt[n]);
            y = fmaf(h[n], Ct[n], y);
        }
        float zv = xz[(size_t)t * (2 * ED) + ED + e];
        float sz = zv / (1.f + __expf(-zv));
        float v = (y + xv * Dv) * sz;
        __nv_bfloat16 hb = __float2bfloat16(v);
        yzh[(size_t)t * ED + e] = hb;
        yzl[(size_t)t * ED + e] = __float2bfloat16(v - __bfloat162float(hb));
    }
}

// ---------------- host orchestration ----------------
extern "C" void kernel_launch(void* const* d_in, const int* in_sizes, int n_in,
                              void* d_out, int out_size) {
    const int*   tokens  = (const int*)d_in[0];
    const float* emb     = (const float*)d_in[1];
    const float* norm_w  = (const float*)d_in[2];
    const float* in_proj = (const float*)d_in[3];
    const float* conv_w  = (const float*)d_in[4];
    const float* conv_b  = (const float*)d_in[5];
    const float* x_proj  = (const float*)d_in[6];
    const float* dt_w    = (const float*)d_in[7];
    const float* dt_b    = (const float*)d_in[8];
    const float* A_log   = (const float*)d_in[9];
    const float* Dp      = (const float*)d_in[10];
    const float* out_prj = (const float*)d_in[11];
    const float* norm_f  = (const float*)d_in[12];
    const float* lm_head = (const float*)d_in[13];
    float* logits = (float*)d_out;

    float *x, *xz, *xb, *dbc, *delta, *cp, *cs, *cc;
    __nv_bfloat16 *ah, *al, *dh, *dl, *wh, *wl;
    cudaGetSymbolAddress((void**)&x,     g_x);
    cudaGetSymbolAddress((void**)&xz,    g_xz);
    cudaGetSymbolAddress((void**)&xb,    g_xb);
    cudaGetSymbolAddress((void**)&dbc,   g_dbc);
    cudaGetSymbolAddress((void**)&delta, g_delta);
    cudaGetSymbolAddress((void**)&cp,    g_cp);
    cudaGetSymbolAddress((void**)&cs,    g_cs);
    cudaGetSymbolAddress((void**)&cc,    g_cc);
    cudaGetSymbolAddress((void**)&ah,    g_ah);
    cudaGetSymbolAddress((void**)&al,    g_al);
    cudaGetSymbolAddress((void**)&dh,    g_dh);
    cudaGetSymbolAddress((void**)&dl,    g_dl);
    cudaGetSymbolAddress((void**)&wh,    g_wh);
    cudaGetSymbolAddress((void**)&wl,    g_wl);

    const int SM4 = 2 * (2 * 4 * 32 * ROWB + 2 * 128 * ROWB);   // 81920
    const int SM2 = 2 * (2 * 2 * 32 * ROWB + 2 * 128 * ROWB);   // 61440
    const int SM1 = 2 * (2 * 1 * 32 * ROWB + 2 * 128 * ROWB);   // 51200
    static bool attr_done = false;
    if (!attr_done) {
        cudaFuncSetAttribute(hgemm_k<2,0>, cudaFuncAttributeMaxDynamicSharedMemorySize, SM2);
        cudaFuncSetAttribute(hgemm_k<2,2>, cudaFuncAttributeMaxDynamicSharedMemorySize, SM2);
        cudaFuncSetAttribute(hgemm_k<1,0>, cudaFuncAttributeMaxDynamicSharedMemorySize, SM1);
        cudaFuncSetAttribute(hgemm_k<4,1>, cudaFuncAttributeMaxDynamicSharedMemorySize, SM4);
        cudaFuncSetAttribute(hgemm_k<4,0>, cudaFuncAttributeMaxDynamicSharedMemorySize, SM4);
        attr_done = true;
    }

    embed_k<<<(L * D + 255) / 256, 256>>>(tokens, emb, x);

    for (int l = 0; l < NL; l++) {
        rmsnorm_split_k<<<L, 256>>>(x, norm_w + l * D, ah, al);

        // xz = xn @ in_proj^T
        int nwi = 2 * ED * D;
        split4_k<<<(nwi / 4 + 255) / 256, 256>>>(
            (const float4*)(in_proj + (size_t)l * nwi), (__nv_bfloat162*)wh, (__nv_bfloat162*)wl, nwi / 4);
        hgemm_k<2,0><<<dim3(L / 64, 2 * ED / 128), 256, SM2>>>(
            ah, al, wh, wl, xz, D, 2 * ED, 2 * ED, nullptr);

        // conv + silu (also emits bf16 hi/lo of xb into ah/al)
        conv_silu_split_k<<<(L * ED + 255) / 256, 256>>>(
            xz, conv_w + (size_t)l * ED * DCONV, conv_b + l * ED, xb, ah, al);

        // dbc = xb @ x_proj^T  (N=80 padded to 128)
        split_pad_k<<<(128 * ED + 255) / 256, 256>>>(
            x_proj + (size_t)l * DXP * ED, wh, wl, 128, ED, DXP, ED, ED);
        hgemm_k<1,0><<<dim3(L / 32, 1), 256, SM1>>>(
            ah, al, wh, wl, dbc, ED, DXP, DXP, nullptr);

        // delta = softplus(dbc[:, :48] @ dt_w^T + dt_b)   (K=48 padded to 64)
        split_pad_k<<<(L * 64 + 255) / 256, 256>>>(dbc, dh, dl, L, 64, L, DTR, DXP);
        split_pad_k<<<(ED * 64 + 255) / 256, 256>>>(
            dt_w + (size_t)l * ED * DTR, wh, wl, ED, 64, ED, DTR, DTR);
        hgemm_k<4,1><<<dim3(L / 128, ED / 128), 256, SM4>>>(
            dh, dl, wh, wl, delta, 64, ED, ED, dt_b + l * ED);

        // selective scan (writes gated output as bf16 hi/lo into ah/al)
        scan1_k<<<(NCHUNK * ED) / 256, 256>>>(delta, xb, dbc,
                                              A_log + (size_t)l * ED * NST, cp, cs);
        carry_k<<<(ED * NST) / 256, 256>>>(cp, cs, cc);
        scan2_k<<<(NCHUNK * ED) / 256, 256>>>(delta, xb, dbc,
                                              A_log + (size_t)l * ED * NST, cc,
                                              Dp + l * ED, xz, ah, al);

        // x += yz @ out_proj^T
        int nwo = D * ED;
        split4_k<<<(nwo / 4 + 255) / 256, 256>>>(
            (const float4*)(out_prj + (size_t)l * nwo), (__nv_bfloat162*)wh, (__nv_bfloat162*)wl, nwo / 4);
        hgemm_k<2,2><<<dim3(L / 64, D / 128), 256, SM2>>>(
            ah, al, wh, wl, x, ED, D, D, nullptr);
    }

    rmsnorm_split_k<<<L, 256>>>(x, norm_f, ah, al);

    // logits = xn @ lm_head^T
    int nwl = VOCAB * D;
    split4_k<<<(nwl / 4 + 255) / 256, 256>>>(
        (const float4*)lm_head, (__nv_bfloat162*)wh, (__nv_bfloat162*)wl, nwl / 4);
    hgemm_k<4,0><<<dim3(L / 128, VOCAB / 128), 256, SM4>>>(
        ah, al, wh, wl, logits, D, VOCAB, VOCAB, nullptr);
}